// round 8
// baseline (speedup 1.0000x reference)
#include <cuda_runtime.h>
#include <math.h>
#include <stdint.h>

#define B_ 4
#define T_ 2048
#define C_ 1024
#define H_ 16
#define D_ 64
#define C3_ (3 * C_)
#define M_ (B_ * T_)

// ---------------------------------------------------------------------------
// Scratch (no cudaMalloc allowed)
// ---------------------------------------------------------------------------
__device__ float g_xa[(size_t)M_ * C_];       // x rounded to tf32
__device__ float g_wkqvT[(size_t)C3_ * C_];   // W_kqv^T [3C, C], tf32-rounded
__device__ float g_wprojT[(size_t)C_ * C_];   // W_proj^T [C, C], tf32-rounded
__device__ float g_kqv[(size_t)M_ * C3_];     // [B*T, 3C]  k|q|v (tf32-rounded)
__device__ float g_y[(size_t)M_ * C_];        // attention out (tf32-rounded)

__device__ __forceinline__ float tf32r(float v) {
    float o;
    asm("cvt.rna.tf32.f32 %0, %1;" : "=f"(o) : "f"(v));
    return o;
}
__device__ __forceinline__ float ex2(float x) {
    float y;
    asm("ex2.approx.f32 %0, %1;" : "=f"(y) : "f"(x));
    return y;
}

// mma.sync m16n8k8 tf32: D = A*B + C (fp32 accum)
__device__ __forceinline__ void mma_tf32(
    float c[4], uint32_t a0, uint32_t a1, uint32_t a2, uint32_t a3,
    uint32_t b0, uint32_t b1)
{
    asm volatile(
        "mma.sync.aligned.m16n8k8.row.col.f32.tf32.tf32.f32 "
        "{%0,%1,%2,%3}, {%4,%5,%6,%7}, {%8,%9}, {%0,%1,%2,%3};"
        : "+f"(c[0]), "+f"(c[1]), "+f"(c[2]), "+f"(c[3])
        : "r"(a0), "r"(a1), "r"(a2), "r"(a3), "r"(b0), "r"(b1));
}

// ---------------------------------------------------------------------------
// tf32 round (elementwise, vectorized)
// ---------------------------------------------------------------------------
__global__ void __launch_bounds__(256) round_tf32_vec(
    const float* __restrict__ in, float* __restrict__ out, int n4)
{
    int i = blockIdx.x * blockDim.x + threadIdx.x;
    if (i >= n4) return;
    float4 v = ((const float4*)in)[i];
    v.x = tf32r(v.x); v.y = tf32r(v.y); v.z = tf32r(v.z); v.w = tf32r(v.w);
    ((float4*)out)[i] = v;
}

// ---------------------------------------------------------------------------
// Transpose + tf32-round: W [K,N] -> Wt [N,K]
// ---------------------------------------------------------------------------
__global__ void __launch_bounds__(256) transpose_round(
    const float* __restrict__ W, float* __restrict__ Wt, int K, int N)
{
    __shared__ float tile[32][33];
    const int n0 = blockIdx.x * 32, k0 = blockIdx.y * 32;
    #pragma unroll
    for (int i = threadIdx.y; i < 32; i += 8)
        tile[i][threadIdx.x] = W[(size_t)(k0 + i) * N + n0 + threadIdx.x];
    __syncthreads();
    #pragma unroll
    for (int i = threadIdx.y; i < 32; i += 8)
        Wt[(size_t)(n0 + i) * K + k0 + threadIdx.x] = tf32r(tile[threadIdx.x][i]);
}

// ---------------------------------------------------------------------------
// tf32 tensor-core GEMM via mma.sync:
//   C[M,N] = A[M,K] @ Bt[N,K]^T + bias[N]   (optionally tf32-round output)
// CTA tile 128x128, BK=16, 128 threads (4 warps, 2x2), warp tile 64x64.
// 2-stage smem double buffer; pitch 20 (conflict-free fragment reads).
// ---------------------------------------------------------------------------
#define GBM 128
#define GBN 128
#define GBK 16
#define SP  20   // 16 + 4 pad; 20 mod 32 -> frag banks 20g+q all distinct

__global__ void __launch_bounds__(128, 2) gemm_tf32_mma(
    const float* __restrict__ A, const float* __restrict__ Bt,
    const float* __restrict__ bias, float* __restrict__ Cout,
    int M, int N, int K, int roundOut)
{
    __shared__ float As[2][GBM * SP];
    __shared__ float Bs[2][GBN * SP];

    const int tid = threadIdx.x;
    const int wid = tid >> 5;
    const int lane = tid & 31;
    const int g = lane >> 2;
    const int q = lane & 3;

    const int wm = (wid >> 1) * 64;   // 0 or 64
    const int wn = (wid & 1) * 64;    // 0 or 64

    const int mtile = blockIdx.y;
    const int ntile = blockIdx.x;

    const float* Ag = A + (size_t)mtile * GBM * K;
    const float* Bg = Bt + (size_t)ntile * GBN * K;

    // loader mapping: idx = tid + i*128 ; r = idx>>2 (0..127), c4 = idx&3
    float4 pa[4], pb[4];
    #pragma unroll
    for (int i = 0; i < 4; i++) {
        const int idx = tid + i * 128;
        const int r = idx >> 2, c4 = idx & 3;
        pa[i] = *(const float4*)(Ag + (size_t)r * K + c4 * 4);
        pb[i] = *(const float4*)(Bg + (size_t)r * K + c4 * 4);
    }
    #pragma unroll
    for (int i = 0; i < 4; i++) {
        const int idx = tid + i * 128;
        const int r = idx >> 2, c4 = idx & 3;
        *(float4*)&As[0][r * SP + c4 * 4] = pa[i];
        *(float4*)&Bs[0][r * SP + c4 * 4] = pb[i];
    }
    __syncthreads();

    float acc[4][8][4];
    #pragma unroll
    for (int mi = 0; mi < 4; mi++)
        #pragma unroll
        for (int ni = 0; ni < 8; ni++)
            #pragma unroll
            for (int r = 0; r < 4; r++) acc[mi][ni][r] = 0.f;

    const int nchunk = K / GBK;
    for (int ch = 0; ch < nchunk; ch++) {
        const int cur = ch & 1, nxt = cur ^ 1;

        if (ch + 1 < nchunk) {
            const int k0 = (ch + 1) * GBK;
            #pragma unroll
            for (int i = 0; i < 4; i++) {
                const int idx = tid + i * 128;
                const int r = idx >> 2, c4 = idx & 3;
                pa[i] = *(const float4*)(Ag + (size_t)r * K + k0 + c4 * 4);
                pb[i] = *(const float4*)(Bg + (size_t)r * K + k0 + c4 * 4);
            }
        }

        #pragma unroll
        for (int ks = 0; ks < GBK; ks += 8) {
            uint32_t af[4][4], bf[8][2];
            #pragma unroll
            for (int mi = 0; mi < 4; mi++) {
                const int mo = wm + mi * 16;
                af[mi][0] = __float_as_uint(As[cur][(mo + g) * SP + ks + q]);
                af[mi][1] = __float_as_uint(As[cur][(mo + 8 + g) * SP + ks + q]);
                af[mi][2] = __float_as_uint(As[cur][(mo + g) * SP + ks + q + 4]);
                af[mi][3] = __float_as_uint(As[cur][(mo + 8 + g) * SP + ks + q + 4]);
            }
            #pragma unroll
            for (int ni = 0; ni < 8; ni++) {
                const int no = wn + ni * 8;
                bf[ni][0] = __float_as_uint(Bs[cur][(no + g) * SP + ks + q]);
                bf[ni][1] = __float_as_uint(Bs[cur][(no + g) * SP + ks + q + 4]);
            }
            #pragma unroll
            for (int mi = 0; mi < 4; mi++)
                #pragma unroll
                for (int ni = 0; ni < 8; ni++)
                    mma_tf32(acc[mi][ni], af[mi][0], af[mi][1], af[mi][2], af[mi][3],
                             bf[ni][0], bf[ni][1]);
        }

        if (ch + 1 < nchunk) {
            #pragma unroll
            for (int i = 0; i < 4; i++) {
                const int idx = tid + i * 128;
                const int r = idx >> 2, c4 = idx & 3;
                *(float4*)&As[nxt][r * SP + c4 * 4] = pa[i];
                *(float4*)&Bs[nxt][r * SP + c4 * 4] = pb[i];
            }
        }
        __syncthreads();
    }

    const int rowbase = mtile * GBM + wm;
    const int colbase = ntile * GBN + wn;
    #pragma unroll
    for (int mi = 0; mi < 4; mi++) {
        #pragma unroll
        for (int ni = 0; ni < 8; ni++) {
            const int col = colbase + ni * 8 + 2 * q;
            const float bx = bias[col], by = bias[col + 1];
            const int r0 = rowbase + mi * 16 + g;
            float2 v0 = make_float2(acc[mi][ni][0] + bx, acc[mi][ni][1] + by);
            float2 v1 = make_float2(acc[mi][ni][2] + bx, acc[mi][ni][3] + by);
            if (roundOut) {
                v0.x = tf32r(v0.x); v0.y = tf32r(v0.y);
                v1.x = tf32r(v1.x); v1.y = tf32r(v1.y);
            }
            *(float2*)(Cout + (size_t)r0 * N + col) = v0;
            *(float2*)(Cout + (size_t)(r0 + 8) * N + col) = v1;
        }
    }
}

// ---------------------------------------------------------------------------
// Tensor-core flash attention (tf32 mma.sync), causal + padding mask.
// CTA: 64 queries x one (b,h). 4 warps, each owns 16 query rows.
// Pitch 68 (== 4 mod 32). K buffer reused for V. Softmax in log2 domain.
// ---------------------------------------------------------------------------
#define FBQ 64
#define FKV 64
#define KP  68   // 64 + 4 pad

__global__ void __launch_bounds__(128) flash_attn_tc(
    const float* __restrict__ kqv, const int* __restrict__ pmask,
    float* __restrict__ y)
{
    __shared__ float KVsh[FKV * KP];   // K tile, then reused for V
    __shared__ float PQsh[FBQ * KP];   // Q tile first, then reused for P
    __shared__ int   pm_sh[FKV];

    const int qt = (T_ / FBQ - 1) - blockIdx.x;   // long CTAs first
    const int bh = blockIdx.y;
    const int b  = bh / H_;
    const int h  = bh % H_;
    const int tid = threadIdx.x;
    const int wid = tid >> 5, lane = tid & 31;
    const int g = lane >> 2, q = lane & 3;
    const int m0 = wid * 16;

    const float* base = kqv + (size_t)b * T_ * C3_ + h * D_;
    const int* pmrow = pmask + b * T_;

    // ---- load Q tile, scale by log2(e)/sqrt(D), re-round to tf32 ----
    const float qscale = 0.125f * 1.4426950408889634f;
    {
        const float* Qg = base + C_;
        #pragma unroll
        for (int it = 0; it < 8; it++) {
            int idx = tid + it * 128;
            int r = idx >> 4, c4 = idx & 15;
            float4 v = *(const float4*)(Qg + (size_t)(qt * FBQ + r) * C3_ + c4 * 4);
            v.x = tf32r(v.x * qscale); v.y = tf32r(v.y * qscale);
            v.z = tf32r(v.z * qscale); v.w = tf32r(v.w * qscale);
            *(float4*)&PQsh[r * KP + c4 * 4] = v;
        }
    }
    __syncthreads();

    // ---- Q fragments to registers (held whole kernel) ----
    uint32_t qf[8][4];
    #pragma unroll
    for (int kk = 0; kk < 8; kk++) {
        qf[kk][0] = __float_as_uint(PQsh[(m0 + g) * KP + kk * 8 + q]);
        qf[kk][1] = __float_as_uint(PQsh[(m0 + 8 + g) * KP + kk * 8 + q]);
        qf[kk][2] = __float_as_uint(PQsh[(m0 + g) * KP + kk * 8 + q + 4]);
        qf[kk][3] = __float_as_uint(PQsh[(m0 + 8 + g) * KP + kk * 8 + q + 4]);
    }
    __syncthreads();

    float o[8][4];
    #pragma unroll
    for (int ni = 0; ni < 8; ni++)
        #pragma unroll
        for (int r = 0; r < 4; r++) o[ni][r] = 0.f;

    float mr0 = -INFINITY, mr1 = -INFINITY;   // running row max (log2 units)
    float l0 = 0.f, l1 = 0.f;                 // lane-partial row sums

    const int r0g = qt * FBQ + m0 + g;        // global query rows
    const int r1g = r0g + 8;

    for (int kt = 0; kt <= qt; kt++) {
        const int kbase = kt * FKV;

        // ---- load K tile ----
        #pragma unroll
        for (int it = 0; it < 8; it++) {
            int idx = tid + it * 128;
            int r = idx >> 4, c4 = idx & 15;
            const float* rowp = base + (size_t)(kbase + r) * C3_;
            *(float4*)&KVsh[r * KP + c4 * 4] = *(const float4*)(rowp + c4 * 4);
        }
        if (tid < FKV) pm_sh[tid] = pmrow[kbase + tid];
        __syncthreads();

        // ---- S = Q K^T (per-warp 16x64), log2-scaled ----
        float s[8][4];
        #pragma unroll
        for (int ni = 0; ni < 8; ni++)
            #pragma unroll
            for (int r = 0; r < 4; r++) s[ni][r] = 0.f;

        #pragma unroll
        for (int kk = 0; kk < 8; kk++) {
            #pragma unroll
            for (int ni = 0; ni < 8; ni++) {
                uint32_t b0 = __float_as_uint(KVsh[(ni * 8 + g) * KP + kk * 8 + q]);
                uint32_t b1 = __float_as_uint(KVsh[(ni * 8 + g) * KP + kk * 8 + q + 4]);
                mma_tf32(s[ni], qf[kk][0], qf[kk][1], qf[kk][2], qf[kk][3], b0, b1);
            }
        }
        __syncthreads();   // K reads done; KVsh free for V

        // ---- load V tile into KVsh (overlaps with softmax below) ----
        #pragma unroll
        for (int it = 0; it < 8; it++) {
            int idx = tid + it * 128;
            int r = idx >> 4, c4 = idx & 15;
            const float* rowp = base + (size_t)(kbase + r) * C3_ + 2 * C_;
            *(float4*)&KVsh[r * KP + c4 * 4] = *(const float4*)(rowp + c4 * 4);
        }

        // ---- mask + tile max ----
        const bool diag = (kt == qt);
        float mt0 = -INFINITY, mt1 = -INFINITY;
        #pragma unroll
        for (int ni = 0; ni < 8; ni++) {
            const int c0 = ni * 8 + 2 * q, c1 = c0 + 1;
            const bool pm0 = pm_sh[c0] != 0, pm1 = pm_sh[c1] != 0;
            const int gc0 = kbase + c0, gc1 = kbase + c1;
            if (!(pm0 && (!diag || gc0 <= r0g))) s[ni][0] = -1e30f;
            if (!(pm1 && (!diag || gc1 <= r0g))) s[ni][1] = -1e30f;
            if (!(pm0 && (!diag || gc0 <= r1g))) s[ni][2] = -1e30f;
            if (!(pm1 && (!diag || gc1 <= r1g))) s[ni][3] = -1e30f;
            mt0 = fmaxf(mt0, fmaxf(s[ni][0], s[ni][1]));
            mt1 = fmaxf(mt1, fmaxf(s[ni][2], s[ni][3]));
        }
        mt0 = fmaxf(mt0, __shfl_xor_sync(0xffffffffu, mt0, 1));
        mt0 = fmaxf(mt0, __shfl_xor_sync(0xffffffffu, mt0, 2));
        mt1 = fmaxf(mt1, __shfl_xor_sync(0xffffffffu, mt1, 1));
        mt1 = fmaxf(mt1, __shfl_xor_sync(0xffffffffu, mt1, 2));

        const float mn0 = fmaxf(mr0, mt0), mn1 = fmaxf(mr1, mt1);
        const float ms0 = (mn0 < -1e29f) ? 0.f : mn0;
        const float ms1 = (mn1 < -1e29f) ? 0.f : mn1;
        const float corr0 = ex2(mr0 - ms0);   // 0 when mr0 == -inf
        const float corr1 = ex2(mr1 - ms1);
        mr0 = mn0; mr1 = mn1;
        l0 *= corr0; l1 *= corr1;
        #pragma unroll
        for (int ni = 0; ni < 8; ni++) {
            o[ni][0] *= corr0; o[ni][1] *= corr0;
            o[ni][2] *= corr1; o[ni][3] *= corr1;
        }

        // ---- P = 2^(S - m), store tf32 to smem (own warp rows only) ----
        #pragma unroll
        for (int ni = 0; ni < 8; ni++) {
            float p0 = ex2(s[ni][0] - ms0);
            float p1 = ex2(s[ni][1] - ms0);
            float p2 = ex2(s[ni][2] - ms1);
            float p3 = ex2(s[ni][3] - ms1);
            l0 += p0 + p1; l1 += p2 + p3;
            *(float2*)&PQsh[(m0 + g) * KP + ni * 8 + 2 * q] =
                make_float2(tf32r(p0), tf32r(p1));
            *(float2*)&PQsh[(m0 + 8 + g) * KP + ni * 8 + 2 * q] =
                make_float2(tf32r(p2), tf32r(p3));
        }
        __syncthreads();   // V tile fully stored + P visible

        // ---- O += P V  (V read transposed from [keys][d] layout) ----
        #pragma unroll
        for (int kk = 0; kk < 8; kk++) {
            uint32_t a0 = __float_as_uint(PQsh[(m0 + g) * KP + kk * 8 + q]);
            uint32_t a1 = __float_as_uint(PQsh[(m0 + 8 + g) * KP + kk * 8 + q]);
            uint32_t a2 = __float_as_uint(PQsh[(m0 + g) * KP + kk * 8 + q + 4]);
            uint32_t a3 = __float_as_uint(PQsh[(m0 + 8 + g) * KP + kk * 8 + q + 4]);
            #pragma unroll
            for (int ni = 0; ni < 8; ni++) {
                uint32_t b0 = __float_as_uint(KVsh[(kk * 8 + q) * KP + ni * 8 + g]);
                uint32_t b1 = __float_as_uint(KVsh[(kk * 8 + q + 4) * KP + ni * 8 + g]);
                mma_tf32(o[ni], a0, a1, a2, a3, b0, b1);
            }
        }
        __syncthreads();   // PV done before next K load overwrites KVsh
    }

    // ---- finalize: full row sums, normalize, write y (tf32-rounded) ----
    l0 += __shfl_xor_sync(0xffffffffu, l0, 1);
    l0 += __shfl_xor_sync(0xffffffffu, l0, 2);
    l1 += __shfl_xor_sync(0xffffffffu, l1, 1);
    l1 += __shfl_xor_sync(0xffffffffu, l1, 2);
    const float inv0 = 1.f / l0, inv1 = 1.f / l1;

    float* yb = y + (size_t)b * T_ * C_ + h * D_;
    #pragma unroll
    for (int ni = 0; ni < 8; ni++) {
        const int col = ni * 8 + 2 * q;
        *(float2*)&yb[(size_t)r0g * C_ + col] =
            make_float2(tf32r(o[ni][0] * inv0), tf32r(o[ni][1] * inv0));
        *(float2*)&yb[(size_t)r1g * C_ + col] =
            make_float2(tf32r(o[ni][2] * inv1), tf32r(o[ni][3] * inv1));
    }
}

// ---------------------------------------------------------------------------
extern "C" void kernel_launch(void* const* d_in, const int* in_sizes, int n_in,
                              void* d_out, int out_size)
{
    const float* x      = (const float*)d_in[0];   // [B,T,C]
    const float* W_kqv  = (const float*)d_in[1];   // [C,3C]
    const float* b_kqv  = (const float*)d_in[2];   // [3C]
    const float* W_proj = (const float*)d_in[3];   // [C,C]
    const float* b_proj = (const float*)d_in[4];   // [C]
    const int*   pmask  = (const int*)d_in[5];     // [B,T]
    float* out = (float*)d_out;                    // [B,T,C]

    float *xa, *wkqvT, *wprojT, *kqv, *y;
    cudaGetSymbolAddress((void**)&xa, g_xa);
    cudaGetSymbolAddress((void**)&wkqvT, g_wkqvT);
    cudaGetSymbolAddress((void**)&wprojT, g_wprojT);
    cudaGetSymbolAddress((void**)&kqv, g_kqv);
    cudaGetSymbolAddress((void**)&y, g_y);

    // 0) tf32-round x; transpose+round weights
    {
        int n4 = M_ * C_ / 4;
        round_tf32_vec<<<(n4 + 255) / 256, 256>>>(x, xa, n4);
        dim3 g1(C3_ / 32, C_ / 32);
        transpose_round<<<g1, dim3(32, 8)>>>(W_kqv, wkqvT, C_, C3_);
        dim3 g2(C_ / 32, C_ / 32);
        transpose_round<<<g2, dim3(32, 8)>>>(W_proj, wprojT, C_, C_);
    }
    // 1) kqv = xa @ W_kqv + b_kqv   (tf32 mma.sync; output tf32-rounded)
    {
        dim3 grid(C3_ / GBN, M_ / GBM);
        gemm_tf32_mma<<<grid, 128>>>(xa, wkqvT, b_kqv, kqv, M_, C3_, C_, 1);
    }
    // 2) flash attention (tf32 mma.sync)
    {
        dim3 grid(T_ / FBQ, B_ * H_);
        flash_attn_tc<<<grid, 128>>>(kqv, pmask, y);
    }
    // 3) out = y @ W_proj + b_proj  (tf32 mma.sync; fp32 output)
    {
        dim3 grid(C_ / GBN, M_ / GBM);
        gemm_tf32_mma<<<grid, 128>>>(y, wprojT, b_proj, out, M_, C_, C_, 0);
    }
}

// round 9
// speedup vs baseline: 1.8189x; 1.8189x over previous
#include <cuda_runtime.h>
#include <cuda_fp16.h>
#include <math.h>
#include <stdint.h>

#define B_ 4
#define T_ 2048
#define C_ 1024
#define H_ 16
#define D_ 64
#define C3_ (3 * C_)
#define M_ (B_ * T_)
#define K2_ (C_ / 2)          // 512 words (fp16 pairs)
#define KQV_W (C3_ / 2)       // 1536 words per token row
#define YW (C_ / 2)           // 512 words per token row

// ---------------------------------------------------------------------------
// Scratch (no cudaMalloc allowed)
// ---------------------------------------------------------------------------
__device__ uint32_t g_xh[(size_t)M_ * K2_];          // x fp16 [M][512w]
__device__ uint32_t g_wkqvTh[(size_t)C3_ * K2_];     // W_kqv^T fp16 [3072][512w]
__device__ uint32_t g_wprojTh[(size_t)C_ * K2_];     // W_proj^T fp16 [1024][512w]
__device__ uint32_t g_kqvh[(size_t)M_ * KQV_W];      // kqv fp16 [M][1536w]
__device__ uint32_t g_vTh[(size_t)B_ * H_ * D_ * (T_ / 2)];  // V^T fp16 [BH][64][1024w]
__device__ uint32_t g_yh[(size_t)M_ * YW];           // attn out fp16 [M][512w]

__device__ __forceinline__ uint32_t pack_h2(float a, float b) {
    __half2 h = __floats2half2_rn(a, b);
    return *reinterpret_cast<uint32_t*>(&h);
}
__device__ __forceinline__ float ex2(float x) {
    float y;
    asm("ex2.approx.f32 %0, %1;" : "=f"(y) : "f"(x));
    return y;
}

// mma.sync m16n8k16 fp16 in, fp32 accum: D = A*B + C
__device__ __forceinline__ void mma_f16(
    float c[4], uint32_t a0, uint32_t a1, uint32_t a2, uint32_t a3,
    uint32_t b0, uint32_t b1)
{
    asm volatile(
        "mma.sync.aligned.m16n8k16.row.col.f32.f16.f16.f32 "
        "{%0,%1,%2,%3}, {%4,%5,%6,%7}, {%8,%9}, {%0,%1,%2,%3};"
        : "+f"(c[0]), "+f"(c[1]), "+f"(c[2]), "+f"(c[3])
        : "r"(a0), "r"(a1), "r"(a2), "r"(a3), "r"(b0), "r"(b1));
}

// ---------------------------------------------------------------------------
// fp32 -> fp16 pairs (words)
// ---------------------------------------------------------------------------
__global__ void __launch_bounds__(256) cvt_f32_to_h2(
    const float* __restrict__ in, uint32_t* __restrict__ out, int nw)
{
    int i = blockIdx.x * blockDim.x + threadIdx.x;
    if (i >= nw) return;
    float2 v = ((const float2*)in)[i];
    out[i] = pack_h2(v.x, v.y);
}

// ---------------------------------------------------------------------------
// Transpose + fp16: W [K,N] fp32 -> Wt [N,K] fp16
// ---------------------------------------------------------------------------
__global__ void __launch_bounds__(256) transpose_h(
    const float* __restrict__ W, __half* __restrict__ Wt, int K, int N)
{
    __shared__ float tile[32][33];
    const int n0 = blockIdx.x * 32, k0 = blockIdx.y * 32;
    #pragma unroll
    for (int i = threadIdx.y; i < 32; i += 8)
        tile[i][threadIdx.x] = W[(size_t)(k0 + i) * N + n0 + threadIdx.x];
    __syncthreads();
    #pragma unroll
    for (int i = threadIdx.y; i < 32; i += 8)
        Wt[(size_t)(n0 + i) * K + k0 + threadIdx.x] = __float2half_rn(tile[threadIdx.x][i]);
}

// ---------------------------------------------------------------------------
// fp16 tensor-core GEMM:  C[M,N] = A[M,K] @ Bt[N,K]^T + bias[N]
// A, Bt fp16 word arrays [.][K2 words]. CTA 128x128, BK=16 words (32 fp16),
// 256 threads (8 warps 2x4, warp tile 64x32), double-buffered, pitch 20 words.
// outHalf: pack fp16-pair output (word pitch N/2), else fp32.
// ---------------------------------------------------------------------------
#define GBK2 16
#define SP 20

__global__ void __launch_bounds__(256, 2) gemm_f16_mma(
    const uint32_t* __restrict__ A, const uint32_t* __restrict__ Bt,
    const float* __restrict__ bias, void* __restrict__ Cout,
    int M, int N, int K2, int outHalf)
{
    __shared__ uint32_t As[2][128 * SP];
    __shared__ uint32_t Bs[2][128 * SP];

    const int tid = threadIdx.x;
    const int wid = tid >> 5;
    const int lane = tid & 31;
    const int g = lane >> 2;
    const int q = lane & 3;

    const int wm = (wid >> 2) * 64;    // 0 or 64
    const int wn = (wid & 3) * 32;     // 0,32,64,96

    const int mtile = blockIdx.y;
    const int ntile = blockIdx.x;

    const uint32_t* Ag = A + (size_t)mtile * 128 * K2;
    const uint32_t* Bg = Bt + (size_t)ntile * 128 * K2;

    // loads: 128 rows x 16 words = 512 uint4; 256 threads -> 2 each/operand
    uint4 pa[2], pb[2];
    #pragma unroll
    for (int i = 0; i < 2; i++) {
        const int idx = tid + i * 256;
        const int r = idx >> 2, c4 = idx & 3;
        pa[i] = *(const uint4*)(Ag + (size_t)r * K2 + c4 * 4);
        pb[i] = *(const uint4*)(Bg + (size_t)r * K2 + c4 * 4);
    }
    #pragma unroll
    for (int i = 0; i < 2; i++) {
        const int idx = tid + i * 256;
        const int r = idx >> 2, c4 = idx & 3;
        *(uint4*)&As[0][r * SP + c4 * 4] = pa[i];
        *(uint4*)&Bs[0][r * SP + c4 * 4] = pb[i];
    }
    __syncthreads();

    float acc[4][4][4];
    #pragma unroll
    for (int mi = 0; mi < 4; mi++)
        #pragma unroll
        for (int ni = 0; ni < 4; ni++)
            #pragma unroll
            for (int r = 0; r < 4; r++) acc[mi][ni][r] = 0.f;

    const int nchunk = K2 / GBK2;
    for (int ch = 0; ch < nchunk; ch++) {
        const int cur = ch & 1, nxt = cur ^ 1;

        if (ch + 1 < nchunk) {
            const int k0 = (ch + 1) * GBK2;
            #pragma unroll
            for (int i = 0; i < 2; i++) {
                const int idx = tid + i * 256;
                const int r = idx >> 2, c4 = idx & 3;
                pa[i] = *(const uint4*)(Ag + (size_t)r * K2 + k0 + c4 * 4);
                pb[i] = *(const uint4*)(Bg + (size_t)r * K2 + k0 + c4 * 4);
            }
        }

        #pragma unroll
        for (int ks = 0; ks < GBK2; ks += 8) {    // one k16 step = 8 words
            uint32_t af[4][4], bf[4][2];
            #pragma unroll
            for (int mi = 0; mi < 4; mi++) {
                const int mo = wm + mi * 16;
                af[mi][0] = As[cur][(mo + g) * SP + ks + q];
                af[mi][1] = As[cur][(mo + 8 + g) * SP + ks + q];
                af[mi][2] = As[cur][(mo + g) * SP + ks + q + 4];
                af[mi][3] = As[cur][(mo + 8 + g) * SP + ks + q + 4];
            }
            #pragma unroll
            for (int ni = 0; ni < 4; ni++) {
                const int no = wn + ni * 8;
                bf[ni][0] = Bs[cur][(no + g) * SP + ks + q];
                bf[ni][1] = Bs[cur][(no + g) * SP + ks + q + 4];
            }
            #pragma unroll
            for (int mi = 0; mi < 4; mi++)
                #pragma unroll
                for (int ni = 0; ni < 4; ni++)
                    mma_f16(acc[mi][ni], af[mi][0], af[mi][1], af[mi][2], af[mi][3],
                            bf[ni][0], bf[ni][1]);
        }

        if (ch + 1 < nchunk) {
            #pragma unroll
            for (int i = 0; i < 2; i++) {
                const int idx = tid + i * 256;
                const int r = idx >> 2, c4 = idx & 3;
                *(uint4*)&As[nxt][r * SP + c4 * 4] = pa[i];
                *(uint4*)&Bs[nxt][r * SP + c4 * 4] = pb[i];
            }
        }
        __syncthreads();
    }

    const int rowbase = mtile * 128 + wm;
    const int colbase = ntile * 128 + wn;
    if (outHalf) {
        uint32_t* Ch = (uint32_t*)Cout;
        const int Nw = N >> 1;
        #pragma unroll
        for (int mi = 0; mi < 4; mi++) {
            #pragma unroll
            for (int ni = 0; ni < 4; ni++) {
                const int col = colbase + ni * 8 + 2 * q;
                const float bx = bias[col], by = bias[col + 1];
                const int r0 = rowbase + mi * 16 + g;
                const int wcol = col >> 1;
                Ch[(size_t)r0 * Nw + wcol] = pack_h2(acc[mi][ni][0] + bx, acc[mi][ni][1] + by);
                Ch[(size_t)(r0 + 8) * Nw + wcol] = pack_h2(acc[mi][ni][2] + bx, acc[mi][ni][3] + by);
            }
        }
    } else {
        float* Cf = (float*)Cout;
        #pragma unroll
        for (int mi = 0; mi < 4; mi++) {
            #pragma unroll
            for (int ni = 0; ni < 4; ni++) {
                const int col = colbase + ni * 8 + 2 * q;
                const float bx = bias[col], by = bias[col + 1];
                const int r0 = rowbase + mi * 16 + g;
                float2 v0 = make_float2(acc[mi][ni][0] + bx, acc[mi][ni][1] + by);
                float2 v1 = make_float2(acc[mi][ni][2] + bx, acc[mi][ni][3] + by);
                *(float2*)(Cf + (size_t)r0 * N + col) = v0;
                *(float2*)(Cf + (size_t)(r0 + 8) * N + col) = v1;
            }
        }
    }
}

// ---------------------------------------------------------------------------
// V transpose per head: kqvh v-part [token][d] -> vT [bh][d][t] (fp16 pairs)
// grid (T/64, B*H), block 128.
// ---------------------------------------------------------------------------
__global__ void __launch_bounds__(128) transpose_v(
    const uint32_t* __restrict__ kqvh, uint32_t* __restrict__ vT)
{
    __shared__ __half vs[64][65];
    const int bh = blockIdx.y;
    const int b = bh / H_, h = bh % H_;
    const int t0 = blockIdx.x * 64;
    const int tid = threadIdx.x;

    // load 64 tokens x 32 words
    #pragma unroll
    for (int it = 0; it < 16; it++) {
        const int idx = tid + it * 128;
        const int r = idx >> 5, c = idx & 31;
        uint32_t w = kqvh[(size_t)(b * T_ + t0 + r) * KQV_W + 2 * (C_ / 2) + h * 32 + c];
        __half2 hv = *reinterpret_cast<__half2*>(&w);
        vs[r][2 * c] = __low2half(hv);
        vs[r][2 * c + 1] = __high2half(hv);
    }
    __syncthreads();

    // write 64 d-rows x 32 words (t-pairs)
    #pragma unroll
    for (int it = 0; it < 16; it++) {
        const int idx = tid + it * 128;
        const int d = idx >> 5, j = idx & 31;
        __half2 hv = __halves2half2(vs[2 * j][d], vs[2 * j + 1][d]);
        vT[((size_t)bh * 64 + d) * (T_ / 2) + (t0 >> 1) + j] =
            *reinterpret_cast<uint32_t*>(&hv);
    }
}

// ---------------------------------------------------------------------------
// fp16 tensor-core flash attention, causal + padding mask.
// CTA: 64 queries x one (b,h), 4 warps x 16 query rows.
// K/Q/P tiles [64][32w] pitch 36; V^T tile [64 d][32w] pitch 36.
// Softmax in log2 domain (Q pre-scaled by log2e/8).
// ---------------------------------------------------------------------------
#define FBQ 64
#define FKV 64
#define AP 36   // word pitch: 32 + 4 (== 4 mod 32, conflict-free frags)

__global__ void __launch_bounds__(128) flash_attn_f16(
    const uint32_t* __restrict__ kqvh, const uint32_t* __restrict__ vT,
    const int* __restrict__ pmask, uint32_t* __restrict__ yh)
{
    __shared__ uint32_t Ksh[FKV * AP];
    __shared__ uint32_t Vsh[FKV * AP];     // V^T: rows = d, cols = key pairs
    __shared__ uint32_t PQsh[FBQ * AP];    // Q first, then P
    __shared__ int pm_sh[FKV];

    const int qt = (T_ / FBQ - 1) - blockIdx.x;
    const int bh = blockIdx.y;
    const int b = bh / H_, h = bh % H_;
    const int tid = threadIdx.x;
    const int wid = tid >> 5, lane = tid & 31;
    const int g = lane >> 2, q = lane & 3;
    const int m0 = wid * 16;

    const uint32_t* baseW = kqvh + (size_t)b * T_ * KQV_W + h * 32;  // K words
    const uint32_t* vTb = vT + (size_t)bh * 64 * (T_ / 2);
    const int* pmrow = pmask + b * T_;

    // ---- load Q tile, scale by log2(e)/sqrt(D), to fp16 ----
    const float qscale = 0.125f * 1.4426950408889634f;
    #pragma unroll
    for (int it = 0; it < 4; it++) {
        const int idx = tid + it * 128;
        const int r = idx >> 3, c4 = idx & 7;
        uint4 w = *(const uint4*)(baseW + (C_ / 2) + (size_t)(qt * FBQ + r) * KQV_W + c4 * 4);
        uint32_t* ww = &w.x;
        uint32_t out[4];
        #pragma unroll
        for (int k = 0; k < 4; k++) {
            __half2 hv = *reinterpret_cast<__half2*>(&ww[k]);
            float2 f = __half22float2(hv);
            out[k] = pack_h2(f.x * qscale, f.y * qscale);
        }
        *(uint4*)&PQsh[r * AP + c4 * 4] = *(uint4*)out;
    }
    __syncthreads();

    // ---- Q fragments (4 k16-steps over D=64) ----
    uint32_t qf[4][4];
    #pragma unroll
    for (int kk = 0; kk < 4; kk++) {
        qf[kk][0] = PQsh[(m0 + g) * AP + kk * 8 + q];
        qf[kk][1] = PQsh[(m0 + 8 + g) * AP + kk * 8 + q];
        qf[kk][2] = PQsh[(m0 + g) * AP + kk * 8 + q + 4];
        qf[kk][3] = PQsh[(m0 + 8 + g) * AP + kk * 8 + q + 4];
    }
    __syncthreads();

    float o[8][4];
    #pragma unroll
    for (int ni = 0; ni < 8; ni++)
        #pragma unroll
        for (int r = 0; r < 4; r++) o[ni][r] = 0.f;

    float mr0 = -INFINITY, mr1 = -INFINITY;
    float l0 = 0.f, l1 = 0.f;

    const int r0g = qt * FBQ + m0 + g;
    const int r1g = r0g + 8;

    for (int kt = 0; kt <= qt; kt++) {
        const int kbase = kt * FKV;

        // ---- load K tile [64 keys][32w] and V^T tile [64 d][32w] ----
        #pragma unroll
        for (int it = 0; it < 4; it++) {
            const int idx = tid + it * 128;
            const int r = idx >> 3, c4 = idx & 7;
            *(uint4*)&Ksh[r * AP + c4 * 4] =
                *(const uint4*)(baseW + (size_t)(kbase + r) * KQV_W + c4 * 4);
            *(uint4*)&Vsh[r * AP + c4 * 4] =
                *(const uint4*)(vTb + (size_t)r * (T_ / 2) + (kbase >> 1) + c4 * 4);
        }
        if (tid < FKV) pm_sh[tid] = pmrow[kbase + tid];
        __syncthreads();

        // ---- S = Q K^T ----
        float s[8][4];
        #pragma unroll
        for (int ni = 0; ni < 8; ni++)
            #pragma unroll
            for (int r = 0; r < 4; r++) s[ni][r] = 0.f;

        #pragma unroll
        for (int kk = 0; kk < 4; kk++) {
            #pragma unroll
            for (int ni = 0; ni < 8; ni++) {
                uint32_t b0 = Ksh[(ni * 8 + g) * AP + kk * 8 + q];
                uint32_t b1 = Ksh[(ni * 8 + g) * AP + kk * 8 + q + 4];
                mma_f16(s[ni], qf[kk][0], qf[kk][1], qf[kk][2], qf[kk][3], b0, b1);
            }
        }

        // ---- mask + tile max ----
        const bool diag = (kt == qt);
        float mt0 = -INFINITY, mt1 = -INFINITY;
        #pragma unroll
        for (int ni = 0; ni < 8; ni++) {
            const int c0 = ni * 8 + 2 * q, c1 = c0 + 1;
            const bool pm0 = pm_sh[c0] != 0, pm1 = pm_sh[c1] != 0;
            const int gc0 = kbase + c0, gc1 = kbase + c1;
            if (!(pm0 && (!diag || gc0 <= r0g))) s[ni][0] = -1e30f;
            if (!(pm1 && (!diag || gc1 <= r0g))) s[ni][1] = -1e30f;
            if (!(pm0 && (!diag || gc0 <= r1g))) s[ni][2] = -1e30f;
            if (!(pm1 && (!diag || gc1 <= r1g))) s[ni][3] = -1e30f;
            mt0 = fmaxf(mt0, fmaxf(s[ni][0], s[ni][1]));
            mt1 = fmaxf(mt1, fmaxf(s[ni][2], s[ni][3]));
        }
        mt0 = fmaxf(mt0, __shfl_xor_sync(0xffffffffu, mt0, 1));
        mt0 = fmaxf(mt0, __shfl_xor_sync(0xffffffffu, mt0, 2));
        mt1 = fmaxf(mt1, __shfl_xor_sync(0xffffffffu, mt1, 1));
        mt1 = fmaxf(mt1, __shfl_xor_sync(0xffffffffu, mt1, 2));

        const float mn0 = fmaxf(mr0, mt0), mn1 = fmaxf(mr1, mt1);
        const float ms0 = (mn0 < -1e29f) ? 0.f : mn0;
        const float ms1 = (mn1 < -1e29f) ? 0.f : mn1;
        const float corr0 = ex2(mr0 - ms0);
        const float corr1 = ex2(mr1 - ms1);
        mr0 = mn0; mr1 = mn1;
        l0 *= corr0; l1 *= corr1;
        #pragma unroll
        for (int ni = 0; ni < 8; ni++) {
            o[ni][0] *= corr0; o[ni][1] *= corr0;
            o[ni][2] *= corr1; o[ni][3] *= corr1;
        }

        // ---- P = 2^(S-m) as fp16 pairs (own warp rows; word = ni*4+q) ----
        #pragma unroll
        for (int ni = 0; ni < 8; ni++) {
            float p0 = ex2(s[ni][0] - ms0);
            float p1 = ex2(s[ni][1] - ms0);
            float p2 = ex2(s[ni][2] - ms1);
            float p3 = ex2(s[ni][3] - ms1);
            l0 += p0 + p1; l1 += p2 + p3;
            PQsh[(m0 + g) * AP + ni * 4 + q] = pack_h2(p0, p1);
            PQsh[(m0 + 8 + g) * AP + ni * 4 + q] = pack_h2(p2, p3);
        }
        __syncwarp();

        // ---- O += P V  (B frags from V^T tile) ----
        #pragma unroll
        for (int kk = 0; kk < 4; kk++) {
            uint32_t a0 = PQsh[(m0 + g) * AP + kk * 8 + q];
            uint32_t a1 = PQsh[(m0 + 8 + g) * AP + kk * 8 + q];
            uint32_t a2 = PQsh[(m0 + g) * AP + kk * 8 + q + 4];
            uint32_t a3 = PQsh[(m0 + 8 + g) * AP + kk * 8 + q + 4];
            #pragma unroll
            for (int ni = 0; ni < 8; ni++) {
                uint32_t b0 = Vsh[(ni * 8 + g) * AP + kk * 8 + q];
                uint32_t b1 = Vsh[(ni * 8 + g) * AP + kk * 8 + q + 4];
                mma_f16(o[ni], a0, a1, a2, a3, b0, b1);
            }
        }
        __syncthreads();   // done with K/V/P before next tile overwrites
    }

    // ---- finalize ----
    l0 += __shfl_xor_sync(0xffffffffu, l0, 1);
    l0 += __shfl_xor_sync(0xffffffffu, l0, 2);
    l1 += __shfl_xor_sync(0xffffffffu, l1, 1);
    l1 += __shfl_xor_sync(0xffffffffu, l1, 2);
    const float inv0 = 1.f / l0, inv1 = 1.f / l1;

    #pragma unroll
    for (int ni = 0; ni < 8; ni++) {
        const int wcol = h * 32 + ni * 4 + q;
        yh[(size_t)(b * T_ + r0g) * YW + wcol] = pack_h2(o[ni][0] * inv0, o[ni][1] * inv0);
        yh[(size_t)(b * T_ + r1g) * YW + wcol] = pack_h2(o[ni][2] * inv1, o[ni][3] * inv1);
    }
}

// ---------------------------------------------------------------------------
extern "C" void kernel_launch(void* const* d_in, const int* in_sizes, int n_in,
                              void* d_out, int out_size)
{
    const float* x      = (const float*)d_in[0];   // [B,T,C]
    const float* W_kqv  = (const float*)d_in[1];   // [C,3C]
    const float* b_kqv  = (const float*)d_in[2];   // [3C]
    const float* W_proj = (const float*)d_in[3];   // [C,C]
    const float* b_proj = (const float*)d_in[4];   // [C]
    const int*   pmask  = (const int*)d_in[5];     // [B,T]
    float* out = (float*)d_out;                    // [B,T,C]

    uint32_t *xh, *wkqvTh, *wprojTh, *kqvh, *vTh, *yh;
    cudaGetSymbolAddress((void**)&xh, g_xh);
    cudaGetSymbolAddress((void**)&wkqvTh, g_wkqvTh);
    cudaGetSymbolAddress((void**)&wprojTh, g_wprojTh);
    cudaGetSymbolAddress((void**)&kqvh, g_kqvh);
    cudaGetSymbolAddress((void**)&vTh, g_vTh);
    cudaGetSymbolAddress((void**)&yh, g_yh);

    // 0) convert x and weights to fp16
    {
        int nw = M_ * C_ / 2;
        cvt_f32_to_h2<<<(nw + 255) / 256, 256>>>(x, xh, nw);
        dim3 g1(C3_ / 32, C_ / 32);
        transpose_h<<<g1, dim3(32, 8)>>>(W_kqv, (__half*)wkqvTh, C_, C3_);
        dim3 g2(C_ / 32, C_ / 32);
        transpose_h<<<g2, dim3(32, 8)>>>(W_proj, (__half*)wprojTh, C_, C_);
    }
    // 1) kqv = x @ W_kqv + b_kqv  (fp16 mma, fp16 output)
    {
        dim3 grid(C3_ / 128, M_ / 128);
        gemm_f16_mma<<<grid, 256>>>(xh, wkqvTh, b_kqv, kqvh, M_, C3_, K2_, 1);
    }
    // 2) V transpose per head
    {
        dim3 grid(T_ / 64, B_ * H_);
        transpose_v<<<grid, 128>>>(kqvh, vTh);
    }
    // 3) flash attention (fp16 mma)
    {
        dim3 grid(T_ / FBQ, B_ * H_);
        flash_attn_f16<<<grid, 128>>>(kqvh, vTh, pmask, yh);
    }
    // 4) out = y @ W_proj + b_proj  (fp16 mma, fp32 output)
    {
        dim3 grid(C_ / 128, M_ / 128);
        gemm_f16_mma<<<grid, 256>>>(yh, wprojTh, b_proj, out, M_, C_, K2_, 0);
    }
}

// round 11
// speedup vs baseline: 1.9580x; 1.0765x over previous
#include <cuda_runtime.h>
#include <cuda_fp16.h>
#include <math.h>
#include <stdint.h>

#define B_ 4
#define T_ 2048
#define C_ 1024
#define H_ 16
#define D_ 64
#define C3_ (3 * C_)
#define M_ (B_ * T_)
#define K2_ (C_ / 2)          // 512 words (fp16 pairs)
#define KQV_W (C3_ / 2)       // 1536 words per token row
#define YW (C_ / 2)           // 512 words per token row

// ---------------------------------------------------------------------------
// Scratch (no cudaMalloc allowed)
// ---------------------------------------------------------------------------
__device__ uint32_t g_xh[(size_t)M_ * K2_];          // x fp16 [M][512w]
__device__ uint32_t g_wkqvTh[(size_t)C3_ * K2_];     // W_kqv^T fp16 [3072][512w]
__device__ uint32_t g_wprojTh[(size_t)C_ * K2_];     // W_proj^T fp16 [1024][512w]
__device__ uint32_t g_kqvh[(size_t)M_ * KQV_W];      // kqv fp16 [M][1536w]
__device__ uint32_t g_vTh[(size_t)B_ * H_ * D_ * (T_ / 2)];  // V^T fp16 [BH][64][1024w]
__device__ uint32_t g_yh[(size_t)M_ * YW];           // attn out fp16 [M][512w]

__device__ __forceinline__ uint32_t pack_h2(float a, float b) {
    __half2 h = __floats2half2_rn(a, b);
    return *reinterpret_cast<uint32_t*>(&h);
}
__device__ __forceinline__ float ex2(float x) {
    float y;
    asm("ex2.approx.f32 %0, %1;" : "=f"(y) : "f"(x));
    return y;
}

// mma.sync m16n8k16 fp16 in, fp32 accum
__device__ __forceinline__ void mma_f16(
    float c[4], uint32_t a0, uint32_t a1, uint32_t a2, uint32_t a3,
    uint32_t b0, uint32_t b1)
{
    asm volatile(
        "mma.sync.aligned.m16n8k16.row.col.f32.f16.f16.f32 "
        "{%0,%1,%2,%3}, {%4,%5,%6,%7}, {%8,%9}, {%0,%1,%2,%3};"
        : "+f"(c[0]), "+f"(c[1]), "+f"(c[2]), "+f"(c[3])
        : "r"(a0), "r"(a1), "r"(a2), "r"(a3), "r"(b0), "r"(b1));
}

// cp.async 16B, L1-bypass
__device__ __forceinline__ void cp_async16(uint32_t smem_addr, const void* gptr) {
    asm volatile("cp.async.cg.shared.global [%0], [%1], 16;"
                 :: "r"(smem_addr), "l"(gptr));
}
#define CP_COMMIT() asm volatile("cp.async.commit_group;" ::: "memory")
#define CP_WAIT(N) asm volatile("cp.async.wait_group %0;" :: "n"(N) : "memory")

// ---------------------------------------------------------------------------
// fp32 -> fp16 pairs
// ---------------------------------------------------------------------------
__global__ void __launch_bounds__(256) cvt_f32_to_h2(
    const float* __restrict__ in, uint32_t* __restrict__ out, int nw)
{
    int i = blockIdx.x * blockDim.x + threadIdx.x;
    if (i >= nw) return;
    float2 v = ((const float2*)in)[i];
    out[i] = pack_h2(v.x, v.y);
}

// ---------------------------------------------------------------------------
// Transpose + fp16: W [K,N] fp32 -> Wt [N,K] fp16
// ---------------------------------------------------------------------------
__global__ void __launch_bounds__(256) transpose_h(
    const float* __restrict__ W, __half* __restrict__ Wt, int K, int N)
{
    __shared__ float tile[32][33];
    const int n0 = blockIdx.x * 32, k0 = blockIdx.y * 32;
    #pragma unroll
    for (int i = threadIdx.y; i < 32; i += 8)
        tile[i][threadIdx.x] = W[(size_t)(k0 + i) * N + n0 + threadIdx.x];
    __syncthreads();
    #pragma unroll
    for (int i = threadIdx.y; i < 32; i += 8)
        Wt[(size_t)(n0 + i) * K + k0 + threadIdx.x] = __float2half_rn(tile[threadIdx.x][i]);
}

// ---------------------------------------------------------------------------
// fp16 tensor-core GEMM with cp.async double buffering:
//   C[M,N] = A[M,K] @ Bt[N,K]^T + bias[N]
// CTA 128x128, BK=16 words (32 fp16), 256 threads (8 warps 2x4, warp 64x32).
// ---------------------------------------------------------------------------
#define GBK2 16
#define SP 20

__global__ void __launch_bounds__(256, 2) gemm_f16_mma(
    const uint32_t* __restrict__ A, const uint32_t* __restrict__ Bt,
    const float* __restrict__ bias, void* __restrict__ Cout,
    int M, int N, int K2, int outHalf)
{
    __shared__ uint32_t As[2][128 * SP];
    __shared__ uint32_t Bs[2][128 * SP];

    const int tid = threadIdx.x;
    const int wid = tid >> 5;
    const int lane = tid & 31;
    const int g = lane >> 2;
    const int q = lane & 3;

    const int wm = (wid >> 2) * 64;
    const int wn = (wid & 3) * 32;

    const int mtile = blockIdx.y;
    const int ntile = blockIdx.x;

    const uint32_t* Ag = A + (size_t)mtile * 128 * K2;
    const uint32_t* Bg = Bt + (size_t)ntile * 128 * K2;

    const uint32_t asA = (uint32_t)__cvta_generic_to_shared(&As[0][0]);
    const uint32_t asB = (uint32_t)__cvta_generic_to_shared(&Bs[0][0]);

    // loader mapping: idx = tid + i*256 ; r = idx>>2 (0..127), c4 = idx&3
    const int lr = tid >> 2, lc = tid & 3;

    // prologue: chunk 0 -> buf 0
    #pragma unroll
    for (int i = 0; i < 2; i++) {
        const int r = lr + i * 64;
        const uint32_t doff = (uint32_t)(r * SP + lc * 4) * 4;
        cp_async16(asA + doff, Ag + (size_t)r * K2 + lc * 4);
        cp_async16(asB + doff, Bg + (size_t)r * K2 + lc * 4);
    }
    CP_COMMIT();

    float acc[4][4][4];
    #pragma unroll
    for (int mi = 0; mi < 4; mi++)
        #pragma unroll
        for (int ni = 0; ni < 4; ni++)
            #pragma unroll
            for (int r = 0; r < 4; r++) acc[mi][ni][r] = 0.f;

    const int nchunk = K2 / GBK2;
    for (int ch = 0; ch < nchunk; ch++) {
        const int cur = ch & 1;

        if (ch + 1 < nchunk) {
            const int k0 = (ch + 1) * GBK2;
            const uint32_t boff = (uint32_t)((cur ^ 1) * 128 * SP) * 4;
            #pragma unroll
            for (int i = 0; i < 2; i++) {
                const int r = lr + i * 64;
                const uint32_t doff = boff + (uint32_t)(r * SP + lc * 4) * 4;
                cp_async16(asA + doff, Ag + (size_t)r * K2 + k0 + lc * 4);
                cp_async16(asB + doff, Bg + (size_t)r * K2 + k0 + lc * 4);
            }
            CP_COMMIT();
            CP_WAIT(1);
        } else {
            CP_WAIT(0);
        }
        __syncthreads();

        #pragma unroll
        for (int ks = 0; ks < GBK2; ks += 8) {
            uint32_t af[4][4], bf[4][2];
            #pragma unroll
            for (int mi = 0; mi < 4; mi++) {
                const int mo = wm + mi * 16;
                af[mi][0] = As[cur][(mo + g) * SP + ks + q];
                af[mi][1] = As[cur][(mo + 8 + g) * SP + ks + q];
                af[mi][2] = As[cur][(mo + g) * SP + ks + q + 4];
                af[mi][3] = As[cur][(mo + 8 + g) * SP + ks + q + 4];
            }
            #pragma unroll
            for (int ni = 0; ni < 4; ni++) {
                const int no = wn + ni * 8;
                bf[ni][0] = Bs[cur][(no + g) * SP + ks + q];
                bf[ni][1] = Bs[cur][(no + g) * SP + ks + q + 4];
            }
            #pragma unroll
            for (int mi = 0; mi < 4; mi++)
                #pragma unroll
                for (int ni = 0; ni < 4; ni++)
                    mma_f16(acc[mi][ni], af[mi][0], af[mi][1], af[mi][2], af[mi][3],
                            bf[ni][0], bf[ni][1]);
        }
        __syncthreads();   // readers done before next iter overwrites other buf
    }

    const int rowbase = mtile * 128 + wm;
    const int colbase = ntile * 128 + wn;
    if (outHalf) {
        uint32_t* Ch = (uint32_t*)Cout;
        const int Nw = N >> 1;
        #pragma unroll
        for (int mi = 0; mi < 4; mi++) {
            #pragma unroll
            for (int ni = 0; ni < 4; ni++) {
                const int col = colbase + ni * 8 + 2 * q;
                const float bx = bias[col], by = bias[col + 1];
                const int r0 = rowbase + mi * 16 + g;
                const int wcol = col >> 1;
                Ch[(size_t)r0 * Nw + wcol] = pack_h2(acc[mi][ni][0] + bx, acc[mi][ni][1] + by);
                Ch[(size_t)(r0 + 8) * Nw + wcol] = pack_h2(acc[mi][ni][2] + bx, acc[mi][ni][3] + by);
            }
        }
    } else {
        float* Cf = (float*)Cout;
        #pragma unroll
        for (int mi = 0; mi < 4; mi++) {
            #pragma unroll
            for (int ni = 0; ni < 4; ni++) {
                const int col = colbase + ni * 8 + 2 * q;
                const float bx = bias[col], by = bias[col + 1];
                const int r0 = rowbase + mi * 16 + g;
                float2 v0 = make_float2(acc[mi][ni][0] + bx, acc[mi][ni][1] + by);
                float2 v1 = make_float2(acc[mi][ni][2] + bx, acc[mi][ni][3] + by);
                *(float2*)(Cf + (size_t)r0 * N + col) = v0;
                *(float2*)(Cf + (size_t)(r0 + 8) * N + col) = v1;
            }
        }
    }
}

// ---------------------------------------------------------------------------
// V transpose per head: kqvh v-part [token][d] -> vT [bh][d][t] (fp16 pairs)
// ---------------------------------------------------------------------------
__global__ void __launch_bounds__(128) transpose_v(
    const uint32_t* __restrict__ kqvh, uint32_t* __restrict__ vT)
{
    __shared__ __half vs[64][65];
    const int bh = blockIdx.y;
    const int b = bh / H_, h = bh % H_;
    const int t0 = blockIdx.x * 64;
    const int tid = threadIdx.x;

    #pragma unroll
    for (int it = 0; it < 16; it++) {
        const int idx = tid + it * 128;
        const int r = idx >> 5, c = idx & 31;
        uint32_t w = kqvh[(size_t)(b * T_ + t0 + r) * KQV_W + 2 * (C_ / 2) + h * 32 + c];
        __half2 hv = *reinterpret_cast<__half2*>(&w);
        vs[r][2 * c] = __low2half(hv);
        vs[r][2 * c + 1] = __high2half(hv);
    }
    __syncthreads();

    #pragma unroll
    for (int it = 0; it < 16; it++) {
        const int idx = tid + it * 128;
        const int d = idx >> 5, j = idx & 31;
        __half2 hv = __halves2half2(vs[2 * j][d], vs[2 * j + 1][d]);
        vT[((size_t)bh * 64 + d) * (T_ / 2) + (t0 >> 1) + j] =
            *reinterpret_cast<uint32_t*>(&hv);
    }
}

// ---------------------------------------------------------------------------
// fp16 flash attention with cp.async double-buffered K/V/pmask.
// CTA: 64 queries x one (b,h), 4 warps x 16 query rows. Softmax in log2.
// ---------------------------------------------------------------------------
#define FBQ 64
#define FKV 64
#define AP 36   // word pitch (== 4 mod 32, conflict-free frags; rows 16B-aligned)
#define ATILE (FKV * AP)

__global__ void __launch_bounds__(128) flash_attn_f16(
    const uint32_t* __restrict__ kqvh, const uint32_t* __restrict__ vT,
    const int* __restrict__ pmask, uint32_t* __restrict__ yh)
{
    __shared__ uint32_t Ksh[2][ATILE];
    __shared__ uint32_t Vsh[2][ATILE];     // V^T: rows = d, cols = key pairs
    __shared__ uint32_t PQsh[FBQ * AP];    // Q first, then P
    __shared__ int pm_sh[2][FKV];

    const int qt = (T_ / FBQ - 1) - blockIdx.x;   // long CTAs first
    const int bh = blockIdx.y;
    const int b = bh / H_, h = bh % H_;
    const int tid = threadIdx.x;
    const int wid = tid >> 5, lane = tid & 31;
    const int g = lane >> 2, q = lane & 3;
    const int m0 = wid * 16;

    const uint32_t* baseW = kqvh + (size_t)b * T_ * KQV_W + h * 32;
    const uint32_t* vTb = vT + (size_t)bh * 64 * (T_ / 2);
    const int* pmrow = pmask + b * T_;

    const uint32_t sK = (uint32_t)__cvta_generic_to_shared(&Ksh[0][0]);
    const uint32_t sV = (uint32_t)__cvta_generic_to_shared(&Vsh[0][0]);
    const uint32_t sPM = (uint32_t)__cvta_generic_to_shared(&pm_sh[0][0]);

    // tile issue: K [64 keys][32w], V^T [64 d][32w], pm [64 ints]
    const int ir = tid >> 3, ic = tid & 7;   // row 0..15 (+16*it), 16B col

    // ---- load Q tile (scalar), scale by log2(e)/sqrt(D) ----
    const float qscale = 0.125f * 1.4426950408889634f;
    #pragma unroll
    for (int it = 0; it < 4; it++) {
        const int idx = tid + it * 128;
        const int r = idx >> 3, c4 = idx & 7;
        uint4 w = *(const uint4*)(baseW + (C_ / 2) + (size_t)(qt * FBQ + r) * KQV_W + c4 * 4);
        uint32_t* ww = &w.x;
        uint32_t out[4];
        #pragma unroll
        for (int k = 0; k < 4; k++) {
            __half2 hv = *reinterpret_cast<__half2*>(&ww[k]);
            float2 f = __half22float2(hv);
            out[k] = pack_h2(f.x * qscale, f.y * qscale);
        }
        *(uint4*)&PQsh[r * AP + c4 * 4] = *(uint4*)out;
    }

    // prologue: prefetch tile 0 into buf 0
    {
        const int kbase = 0;
        #pragma unroll
        for (int it = 0; it < 4; it++) {
            const int r = ir + it * 16;
            const uint32_t doff = (uint32_t)(r * AP + ic * 4) * 4;
            cp_async16(sK + doff, baseW + (size_t)(kbase + r) * KQV_W + ic * 4);
            cp_async16(sV + doff, vTb + (size_t)r * (T_ / 2) + (kbase >> 1) + ic * 4);
        }
        if (tid < 16) cp_async16(sPM + tid * 16, pmrow + kbase + tid * 4);
        CP_COMMIT();
    }
    __syncthreads();   // Q tile visible

    // ---- Q fragments ----
    uint32_t qf[4][4];
    #pragma unroll
    for (int kk = 0; kk < 4; kk++) {
        qf[kk][0] = PQsh[(m0 + g) * AP + kk * 8 + q];
        qf[kk][1] = PQsh[(m0 + 8 + g) * AP + kk * 8 + q];
        qf[kk][2] = PQsh[(m0 + g) * AP + kk * 8 + q + 4];
        qf[kk][3] = PQsh[(m0 + 8 + g) * AP + kk * 8 + q + 4];
    }
    __syncthreads();

    float o[8][4];
    #pragma unroll
    for (int ni = 0; ni < 8; ni++)
        #pragma unroll
        for (int r = 0; r < 4; r++) o[ni][r] = 0.f;

    float mr0 = -INFINITY, mr1 = -INFINITY;
    float l0 = 0.f, l1 = 0.f;

    const int r0g = qt * FBQ + m0 + g;
    const int r1g = r0g + 8;

    for (int kt = 0; kt <= qt; kt++) {
        const int cur = kt & 1;
        const int kbase = kt * FKV;

        if (kt < qt) {
            const int nb = kbase + FKV;
            const uint32_t boff = (uint32_t)((cur ^ 1) * ATILE) * 4;
            #pragma unroll
            for (int it = 0; it < 4; it++) {
                const int r = ir + it * 16;
                const uint32_t doff = boff + (uint32_t)(r * AP + ic * 4) * 4;
                cp_async16(sK + doff, baseW + (size_t)(nb + r) * KQV_W + ic * 4);
                cp_async16(sV + doff, vTb + (size_t)r * (T_ / 2) + (nb >> 1) + ic * 4);
            }
            if (tid < 16) cp_async16(sPM + (cur ^ 1) * 256 + tid * 16, pmrow + nb + tid * 4);
            CP_COMMIT();
            CP_WAIT(1);
        } else {
            CP_WAIT(0);
        }
        __syncthreads();

        // ---- S = Q K^T ----
        float s[8][4];
        #pragma unroll
        for (int ni = 0; ni < 8; ni++)
            #pragma unroll
            for (int r = 0; r < 4; r++) s[ni][r] = 0.f;

        #pragma unroll
        for (int kk = 0; kk < 4; kk++) {
            #pragma unroll
            for (int ni = 0; ni < 8; ni++) {
                uint32_t b0 = Ksh[cur][(ni * 8 + g) * AP + kk * 8 + q];
                uint32_t b1 = Ksh[cur][(ni * 8 + g) * AP + kk * 8 + q + 4];
                mma_f16(s[ni], qf[kk][0], qf[kk][1], qf[kk][2], qf[kk][3], b0, b1);
            }
        }

        // ---- mask + tile max ----
        const bool diag = (kt == qt);
        float mt0 = -INFINITY, mt1 = -INFINITY;
        #pragma unroll
        for (int ni = 0; ni < 8; ni++) {
            const int c0 = ni * 8 + 2 * q, c1 = c0 + 1;
            const bool pm0 = pm_sh[cur][c0] != 0, pm1 = pm_sh[cur][c1] != 0;
            const int gc0 = kbase + c0, gc1 = kbase + c1;
            if (!(pm0 && (!diag || gc0 <= r0g))) s[ni][0] = -1e30f;
            if (!(pm1 && (!diag || gc1 <= r0g))) s[ni][1] = -1e30f;
            if (!(pm0 && (!diag || gc0 <= r1g))) s[ni][2] = -1e30f;
            if (!(pm1 && (!diag || gc1 <= r1g))) s[ni][3] = -1e30f;
            mt0 = fmaxf(mt0, fmaxf(s[ni][0], s[ni][1]));
            mt1 = fmaxf(mt1, fmaxf(s[ni][2], s[ni][3]));
        }
        mt0 = fmaxf(mt0, __shfl_xor_sync(0xffffffffu, mt0, 1));
        mt0 = fmaxf(mt0, __shfl_xor_sync(0xffffffffu, mt0, 2));
        mt1 = fmaxf(mt1, __shfl_xor_sync(0xffffffffu, mt1, 1));
        mt1 = fmaxf(mt1, __shfl_xor_sync(0xffffffffu, mt1, 2));

        const float mn0 = fmaxf(mr0, mt0), mn1 = fmaxf(mr1, mt1);
        const float ms0 = (mn0 < -1e29f) ? 0.f : mn0;
        const float ms1 = (mn1 < -1e29f) ? 0.f : mn1;
        const float corr0 = ex2(mr0 - ms0);
        const float corr1 = ex2(mr1 - ms1);
        mr0 = mn0; mr1 = mn1;
        l0 *= corr0; l1 *= corr1;
        #pragma unroll
        for (int ni = 0; ni < 8; ni++) {
            o[ni][0] *= corr0; o[ni][1] *= corr0;
            o[ni][2] *= corr1; o[ni][3] *= corr1;
        }

        // ---- P = 2^(S-m) fp16 pairs ----
        #pragma unroll
        for (int ni = 0; ni < 8; ni++) {
            float p0 = ex2(s[ni][0] - ms0);
            float p1 = ex2(s[ni][1] - ms0);
            float p2 = ex2(s[ni][2] - ms1);
            float p3 = ex2(s[ni][3] - ms1);
            l0 += p0 + p1; l1 += p2 + p3;
            PQsh[(m0 + g) * AP + ni * 4 + q] = pack_h2(p0, p1);
            PQsh[(m0 + 8 + g) * AP + ni * 4 + q] = pack_h2(p2, p3);
        }
        __syncwarp();

        // ---- O += P V ----
        #pragma unroll
        for (int kk = 0; kk < 4; kk++) {
            uint32_t a0 = PQsh[(m0 + g) * AP + kk * 8 + q];
            uint32_t a1 = PQsh[(m0 + 8 + g) * AP + kk * 8 + q];
            uint32_t a2 = PQsh[(m0 + g) * AP + kk * 8 + q + 4];
            uint32_t a3 = PQsh[(m0 + 8 + g) * AP + kk * 8 + q + 4];
            #pragma unroll
            for (int ni = 0; ni < 8; ni++) {
                uint32_t b0 = Vsh[cur][(ni * 8 + g) * AP + kk * 8 + q];
                uint32_t b1 = Vsh[cur][(ni * 8 + g) * AP + kk * 8 + q + 4];
                mma_f16(o[ni], a0, a1, a2, a3, b0, b1);
            }
        }
        __syncthreads();   // all reads of cur done before it is refilled
    }

    // ---- finalize ----
    l0 += __shfl_xor_sync(0xffffffffu, l0, 1);
    l0 += __shfl_xor_sync(0xffffffffu, l0, 2);
    l1 += __shfl_xor_sync(0xffffffffu, l1, 1);
    l1 += __shfl_xor_sync(0xffffffffu, l1, 2);
    const float inv0 = 1.f / l0, inv1 = 1.f / l1;

    #pragma unroll
    for (int ni = 0; ni < 8; ni++) {
        const int wcol = h * 32 + ni * 4 + q;
        yh[(size_t)(b * T_ + r0g) * YW + wcol] = pack_h2(o[ni][0] * inv0, o[ni][1] * inv0);
        yh[(size_t)(b * T_ + r1g) * YW + wcol] = pack_h2(o[ni][2] * inv1, o[ni][3] * inv1);
    }
}

// ---------------------------------------------------------------------------
extern "C" void kernel_launch(void* const* d_in, const int* in_sizes, int n_in,
                              void* d_out, int out_size)
{
    const float* x      = (const float*)d_in[0];
    const float* W_kqv  = (const float*)d_in[1];
    const float* b_kqv  = (const float*)d_in[2];
    const float* W_proj = (const float*)d_in[3];
    const float* b_proj = (const float*)d_in[4];
    const int*   pmask  = (const int*)d_in[5];
    float* out = (float*)d_out;

    uint32_t *xh, *wkqvTh, *wprojTh, *kqvh, *vTh, *yh;
    cudaGetSymbolAddress((void**)&xh, g_xh);
    cudaGetSymbolAddress((void**)&wkqvTh, g_wkqvTh);
    cudaGetSymbolAddress((void**)&wprojTh, g_wprojTh);
    cudaGetSymbolAddress((void**)&kqvh, g_kqvh);
    cudaGetSymbolAddress((void**)&vTh, g_vTh);
    cudaGetSymbolAddress((void**)&yh, g_yh);

    // 0) convert x and weights to fp16
    {
        int nw = M_ * C_ / 2;
        cvt_f32_to_h2<<<(nw + 255) / 256, 256>>>(x, xh, nw);
        dim3 g1(C3_ / 32, C_ / 32);
        transpose_h<<<g1, dim3(32, 8)>>>(W_kqv, (__half*)wkqvTh, C_, C3_);
        dim3 g2(C_ / 32, C_ / 32);
        transpose_h<<<g2, dim3(32, 8)>>>(W_proj, (__half*)wprojTh, C_, C_);
    }
    // 1) kqv = x @ W_kqv + b_kqv  (fp16 mma, fp16 output)
    {
        dim3 grid(C3_ / 128, M_ / 128);
        gemm_f16_mma<<<grid, 256>>>(xh, wkqvTh, b_kqv, kqvh, M_, C3_, K2_, 1);
    }
    // 2) V transpose per head
    {
        dim3 grid(T_ / 64, B_ * H_);
        transpose_v<<<grid, 128>>>(kqvh, vTh);
    }
    // 3) flash attention (fp16 mma, async pipelined)
    {
        dim3 grid(T_ / FBQ, B_ * H_);
        flash_attn_f16<<<grid, 128>>>(kqvh, vTh, pmask, yh);
    }
    // 4) out = y @ W_proj + b_proj  (fp16 mma, fp32 output)
    {
        dim3 grid(C_ / 128, M_ / 128);
        gemm_f16_mma<<<grid, 256>>>(yh, wprojTh, b_proj, out, M_, C_, K2_, 0);
    }
}

// round 12
// speedup vs baseline: 2.1021x; 1.0736x over previous
#include <cuda_runtime.h>
#include <cuda_fp16.h>
#include <math.h>
#include <stdint.h>

#define B_ 4
#define T_ 2048
#define C_ 1024
#define H_ 16
#define D_ 64
#define C3_ (3 * C_)
#define M_ (B_ * T_)
#define K2_ (C_ / 2)          // 512 words (fp16 pairs)
#define KQV_W (C3_ / 2)       // 1536 words per token row
#define YW (C_ / 2)           // 512 words per token row

// ---------------------------------------------------------------------------
// Scratch (no cudaMalloc allowed)
// ---------------------------------------------------------------------------
__device__ uint32_t g_xh[(size_t)M_ * K2_];
__device__ uint32_t g_wkqvTh[(size_t)C3_ * K2_];
__device__ uint32_t g_wprojTh[(size_t)C_ * K2_];
__device__ uint32_t g_kqvh[(size_t)M_ * KQV_W];
__device__ uint32_t g_vTh[(size_t)B_ * H_ * D_ * (T_ / 2)];
__device__ uint32_t g_yh[(size_t)M_ * YW];

__device__ __forceinline__ uint32_t pack_h2(float a, float b) {
    __half2 h = __floats2half2_rn(a, b);
    return *reinterpret_cast<uint32_t*>(&h);
}
__device__ __forceinline__ float ex2(float x) {
    float y;
    asm("ex2.approx.f32 %0, %1;" : "=f"(y) : "f"(x));
    return y;
}

// mma.sync m16n8k16 fp16 in, fp32 accum
__device__ __forceinline__ void mma_f16(
    float c[4], uint32_t a0, uint32_t a1, uint32_t a2, uint32_t a3,
    uint32_t b0, uint32_t b1)
{
    asm volatile(
        "mma.sync.aligned.m16n8k16.row.col.f32.f16.f16.f32 "
        "{%0,%1,%2,%3}, {%4,%5,%6,%7}, {%8,%9}, {%0,%1,%2,%3};"
        : "+f"(c[0]), "+f"(c[1]), "+f"(c[2]), "+f"(c[3])
        : "r"(a0), "r"(a1), "r"(a2), "r"(a3), "r"(b0), "r"(b1));
}

// ldmatrix x4 (each of 4 m8n8 fp16 matrices distributed across the warp)
__device__ __forceinline__ void ldsm_x4(uint32_t r[4], uint32_t addr) {
    asm volatile(
        "ldmatrix.sync.aligned.m8n8.x4.shared.b16 {%0,%1,%2,%3}, [%4];"
        : "=r"(r[0]), "=r"(r[1]), "=r"(r[2]), "=r"(r[3]) : "r"(addr));
}

// cp.async 16B, L1-bypass
__device__ __forceinline__ void cp_async16(uint32_t smem_addr, const void* gptr) {
    asm volatile("cp.async.cg.shared.global [%0], [%1], 16;"
                 :: "r"(smem_addr), "l"(gptr));
}
#define CP_COMMIT() asm volatile("cp.async.commit_group;" ::: "memory")
#define CP_WAIT(N) asm volatile("cp.async.wait_group %0;" :: "n"(N) : "memory")

// ---------------------------------------------------------------------------
// fp32 -> fp16 pairs
// ---------------------------------------------------------------------------
__global__ void __launch_bounds__(256) cvt_f32_to_h2(
    const float* __restrict__ in, uint32_t* __restrict__ out, int nw)
{
    int i = blockIdx.x * blockDim.x + threadIdx.x;
    if (i >= nw) return;
    float2 v = ((const float2*)in)[i];
    out[i] = pack_h2(v.x, v.y);
}

// ---------------------------------------------------------------------------
// Transpose + fp16: W [K,N] fp32 -> Wt [N,K] fp16
// ---------------------------------------------------------------------------
__global__ void __launch_bounds__(256) transpose_h(
    const float* __restrict__ W, __half* __restrict__ Wt, int K, int N)
{
    __shared__ float tile[32][33];
    const int n0 = blockIdx.x * 32, k0 = blockIdx.y * 32;
    #pragma unroll
    for (int i = threadIdx.y; i < 32; i += 8)
        tile[i][threadIdx.x] = W[(size_t)(k0 + i) * N + n0 + threadIdx.x];
    __syncthreads();
    #pragma unroll
    for (int i = threadIdx.y; i < 32; i += 8)
        Wt[(size_t)(n0 + i) * K + k0 + threadIdx.x] = __float2half_rn(tile[threadIdx.x][i]);
}

// ---------------------------------------------------------------------------
// fp16 GEMM, cp.async double-buffered, ldmatrix fragment loads:
//   C[M,N] = A[M,K] @ Bt[N,K]^T + bias[N]
// CTA 128x128, BK=16 words (32 fp16), 256 threads (8 warps 2x4, warp 64x32).
// ---------------------------------------------------------------------------
#define GBK2 16
#define SP 20
#define GBUFB (128 * SP * 4)   // bytes per buffer stage

__global__ void __launch_bounds__(256, 2) gemm_f16_mma(
    const uint32_t* __restrict__ A, const uint32_t* __restrict__ Bt,
    const float* __restrict__ bias, void* __restrict__ Cout,
    int M, int N, int K2, int outHalf)
{
    __shared__ uint32_t As[2][128 * SP];
    __shared__ uint32_t Bs[2][128 * SP];

    const int tid = threadIdx.x;
    const int wid = tid >> 5;
    const int lane = tid & 31;
    const int g = lane >> 2;
    const int q = lane & 3;
    const int i8 = lane & 7, mh = lane >> 3;   // ldmatrix lane decomposition

    const int wm = (wid >> 2) * 64;
    const int wn = (wid & 3) * 32;

    const int mtile = blockIdx.y;
    const int ntile = blockIdx.x;

    const uint32_t* Ag = A + (size_t)mtile * 128 * K2;
    const uint32_t* Bg = Bt + (size_t)ntile * 128 * K2;

    const uint32_t asA = (uint32_t)__cvta_generic_to_shared(&As[0][0]);
    const uint32_t asB = (uint32_t)__cvta_generic_to_shared(&Bs[0][0]);

    // ldmatrix per-lane base addresses (bytes), ks/buffer added in-loop
    // A: m0 rows0-7 seg0 | m1 rows8-15 seg0 | m2 rows0-7 seg4 | m3 rows8-15 seg4
    uint32_t aAddr[4];
    #pragma unroll
    for (int mi = 0; mi < 4; mi++)
        aAddr[mi] = asA + ((wm + mi * 16 + i8 + (mh & 1) * 8) * SP + (mh >> 1) * 4) * 4;
    // B: m0 (ni0,seg0) | m1 (ni0,seg4) | m2 (ni0+1,seg0) | m3 (ni0+1,seg4)
    uint32_t bAddr[2];
    #pragma unroll
    for (int j = 0; j < 2; j++)
        bAddr[j] = asB + ((wn + (2 * j + (mh >> 1)) * 8 + i8) * SP + (mh & 1) * 4) * 4;

    const int lr = tid >> 2, lc = tid & 3;

    // prologue: chunk 0 -> buf 0
    #pragma unroll
    for (int i = 0; i < 2; i++) {
        const int r = lr + i * 64;
        const uint32_t doff = (uint32_t)(r * SP + lc * 4) * 4;
        cp_async16(asA + doff, Ag + (size_t)r * K2 + lc * 4);
        cp_async16(asB + doff, Bg + (size_t)r * K2 + lc * 4);
    }
    CP_COMMIT();

    float acc[4][4][4];
    #pragma unroll
    for (int mi = 0; mi < 4; mi++)
        #pragma unroll
        for (int ni = 0; ni < 4; ni++)
            #pragma unroll
            for (int r = 0; r < 4; r++) acc[mi][ni][r] = 0.f;

    const int nchunk = K2 / GBK2;
    for (int ch = 0; ch < nchunk; ch++) {
        const int cur = ch & 1;

        if (ch + 1 < nchunk) {
            const int k0 = (ch + 1) * GBK2;
            const uint32_t boff = (uint32_t)((cur ^ 1) * 128 * SP) * 4;
            #pragma unroll
            for (int i = 0; i < 2; i++) {
                const int r = lr + i * 64;
                const uint32_t doff = boff + (uint32_t)(r * SP + lc * 4) * 4;
                cp_async16(asA + doff, Ag + (size_t)r * K2 + k0 + lc * 4);
                cp_async16(asB + doff, Bg + (size_t)r * K2 + k0 + lc * 4);
            }
            CP_COMMIT();
            CP_WAIT(1);
        } else {
            CP_WAIT(0);
        }
        __syncthreads();

        const uint32_t bufoff = (uint32_t)cur * GBUFB;
        #pragma unroll
        for (int ks = 0; ks < GBK2; ks += 8) {
            const uint32_t coff = bufoff + ks * 4;
            uint32_t af[4][4], bf[4][2];
            #pragma unroll
            for (int mi = 0; mi < 4; mi++)
                ldsm_x4(af[mi], aAddr[mi] + coff);
            #pragma unroll
            for (int j = 0; j < 2; j++) {
                uint32_t t[4];
                ldsm_x4(t, bAddr[j] + coff);
                bf[2 * j][0] = t[0]; bf[2 * j][1] = t[1];
                bf[2 * j + 1][0] = t[2]; bf[2 * j + 1][1] = t[3];
            }
            #pragma unroll
            for (int mi = 0; mi < 4; mi++)
                #pragma unroll
                for (int ni = 0; ni < 4; ni++)
                    mma_f16(acc[mi][ni], af[mi][0], af[mi][1], af[mi][2], af[mi][3],
                            bf[ni][0], bf[ni][1]);
        }
        __syncthreads();
    }

    const int rowbase = mtile * 128 + wm;
    const int colbase = ntile * 128 + wn;
    if (outHalf) {
        uint32_t* Ch = (uint32_t*)Cout;
        const int Nw = N >> 1;
        #pragma unroll
        for (int mi = 0; mi < 4; mi++) {
            #pragma unroll
            for (int ni = 0; ni < 4; ni++) {
                const int col = colbase + ni * 8 + 2 * q;
                const float bx = bias[col], by = bias[col + 1];
                const int r0 = rowbase + mi * 16 + g;
                const int wcol = col >> 1;
                Ch[(size_t)r0 * Nw + wcol] = pack_h2(acc[mi][ni][0] + bx, acc[mi][ni][1] + by);
                Ch[(size_t)(r0 + 8) * Nw + wcol] = pack_h2(acc[mi][ni][2] + bx, acc[mi][ni][3] + by);
            }
        }
    } else {
        float* Cf = (float*)Cout;
        #pragma unroll
        for (int mi = 0; mi < 4; mi++) {
            #pragma unroll
            for (int ni = 0; ni < 4; ni++) {
                const int col = colbase + ni * 8 + 2 * q;
                const float bx = bias[col], by = bias[col + 1];
                const int r0 = rowbase + mi * 16 + g;
                float2 v0 = make_float2(acc[mi][ni][0] + bx, acc[mi][ni][1] + by);
                float2 v1 = make_float2(acc[mi][ni][2] + bx, acc[mi][ni][3] + by);
                *(float2*)(Cf + (size_t)r0 * N + col) = v0;
                *(float2*)(Cf + (size_t)(r0 + 8) * N + col) = v1;
            }
        }
    }
}

// ---------------------------------------------------------------------------
// V transpose per head: kqvh v-part [token][d] -> vT [bh][d][t]
// ---------------------------------------------------------------------------
__global__ void __launch_bounds__(128) transpose_v(
    const uint32_t* __restrict__ kqvh, uint32_t* __restrict__ vT)
{
    __shared__ __half vs[64][65];
    const int bh = blockIdx.y;
    const int b = bh / H_, h = bh % H_;
    const int t0 = blockIdx.x * 64;
    const int tid = threadIdx.x;

    #pragma unroll
    for (int it = 0; it < 16; it++) {
        const int idx = tid + it * 128;
        const int r = idx >> 5, c = idx & 31;
        uint32_t w = kqvh[(size_t)(b * T_ + t0 + r) * KQV_W + 2 * (C_ / 2) + h * 32 + c];
        __half2 hv = *reinterpret_cast<__half2*>(&w);
        vs[r][2 * c] = __low2half(hv);
        vs[r][2 * c + 1] = __high2half(hv);
    }
    __syncthreads();

    #pragma unroll
    for (int it = 0; it < 16; it++) {
        const int idx = tid + it * 128;
        const int d = idx >> 5, j = idx & 31;
        __half2 hv = __halves2half2(vs[2 * j][d], vs[2 * j + 1][d]);
        vT[((size_t)bh * 64 + d) * (T_ / 2) + (t0 >> 1) + j] =
            *reinterpret_cast<uint32_t*>(&hv);
    }
}

// ---------------------------------------------------------------------------
// fp16 flash attention: cp.async double-buffered K/V, ldmatrix B-frags,
// P kept in registers (no smem round trip). Softmax in log2 domain.
// ---------------------------------------------------------------------------
#define FBQ 64
#define FKV 64
#define AP 36
#define ATILE (FKV * AP)
#define ATILEB (ATILE * 4)

__global__ void __launch_bounds__(128) flash_attn_f16(
    const uint32_t* __restrict__ kqvh, const uint32_t* __restrict__ vT,
    const int* __restrict__ pmask, uint32_t* __restrict__ yh)
{
    __shared__ uint32_t Ksh[2][ATILE];
    __shared__ uint32_t Vsh[2][ATILE];
    __shared__ uint32_t Qsh[FBQ * AP];
    __shared__ int pm_sh[2][FKV];

    const int qt = (T_ / FBQ - 1) - blockIdx.x;
    const int bh = blockIdx.y;
    const int b = bh / H_, h = bh % H_;
    const int tid = threadIdx.x;
    const int wid = tid >> 5, lane = tid & 31;
    const int g = lane >> 2, q = lane & 3;
    const int i8 = lane & 7, mh = lane >> 3;
    const int m0 = wid * 16;

    const uint32_t* baseW = kqvh + (size_t)b * T_ * KQV_W + h * 32;
    const uint32_t* vTb = vT + (size_t)bh * 64 * (T_ / 2);
    const int* pmrow = pmask + b * T_;

    const uint32_t sK = (uint32_t)__cvta_generic_to_shared(&Ksh[0][0]);
    const uint32_t sV = (uint32_t)__cvta_generic_to_shared(&Vsh[0][0]);
    const uint32_t sPM = (uint32_t)__cvta_generic_to_shared(&pm_sh[0][0]);

    // ldmatrix B-operand base addrs: j covers ni pair (2j, 2j+1)
    uint32_t kAddr[4], vAddr[4];
    #pragma unroll
    for (int j = 0; j < 4; j++) {
        const uint32_t off = (((2 * j + (mh >> 1)) * 8 + i8) * AP + (mh & 1) * 4) * 4;
        kAddr[j] = sK + off;
        vAddr[j] = sV + off;
    }

    const int ir = tid >> 3, ic = tid & 7;

    // ---- load Q tile, scale by log2(e)/sqrt(D) ----
    const float qscale = 0.125f * 1.4426950408889634f;
    #pragma unroll
    for (int it = 0; it < 4; it++) {
        const int idx = tid + it * 128;
        const int r = idx >> 3, c4 = idx & 7;
        uint4 w = *(const uint4*)(baseW + (C_ / 2) + (size_t)(qt * FBQ + r) * KQV_W + c4 * 4);
        uint32_t* ww = &w.x;
        uint32_t out[4];
        #pragma unroll
        for (int k = 0; k < 4; k++) {
            __half2 hv = *reinterpret_cast<__half2*>(&ww[k]);
            float2 f = __half22float2(hv);
            out[k] = pack_h2(f.x * qscale, f.y * qscale);
        }
        *(uint4*)&Qsh[r * AP + c4 * 4] = *(uint4*)out;
    }

    // prologue: prefetch tile 0 into buf 0
    {
        #pragma unroll
        for (int it = 0; it < 4; it++) {
            const int r = ir + it * 16;
            const uint32_t doff = (uint32_t)(r * AP + ic * 4) * 4;
            cp_async16(sK + doff, baseW + (size_t)r * KQV_W + ic * 4);
            cp_async16(sV + doff, vTb + (size_t)r * (T_ / 2) + ic * 4);
        }
        if (tid < 16) cp_async16(sPM + tid * 16, pmrow + tid * 4);
        CP_COMMIT();
    }
    __syncthreads();

    // ---- Q fragments ----
    uint32_t qf[4][4];
    #pragma unroll
    for (int kk = 0; kk < 4; kk++) {
        qf[kk][0] = Qsh[(m0 + g) * AP + kk * 8 + q];
        qf[kk][1] = Qsh[(m0 + 8 + g) * AP + kk * 8 + q];
        qf[kk][2] = Qsh[(m0 + g) * AP + kk * 8 + q + 4];
        qf[kk][3] = Qsh[(m0 + 8 + g) * AP + kk * 8 + q + 4];
    }

    float o[8][4];
    #pragma unroll
    for (int ni = 0; ni < 8; ni++)
        #pragma unroll
        for (int r = 0; r < 4; r++) o[ni][r] = 0.f;

    float mr0 = -INFINITY, mr1 = -INFINITY;
    float l0 = 0.f, l1 = 0.f;

    const int r0g = qt * FBQ + m0 + g;
    const int r1g = r0g + 8;

    for (int kt = 0; kt <= qt; kt++) {
        const int cur = kt & 1;
        const int kbase = kt * FKV;

        if (kt < qt) {
            const int nb = kbase + FKV;
            const uint32_t boff = (uint32_t)((cur ^ 1) * ATILE) * 4;
            #pragma unroll
            for (int it = 0; it < 4; it++) {
                const int r = ir + it * 16;
                const uint32_t doff = boff + (uint32_t)(r * AP + ic * 4) * 4;
                cp_async16(sK + doff, baseW + (size_t)(nb + r) * KQV_W + ic * 4);
                cp_async16(sV + doff, vTb + (size_t)r * (T_ / 2) + (nb >> 1) + ic * 4);
            }
            if (tid < 16) cp_async16(sPM + (cur ^ 1) * 256 + tid * 16, pmrow + nb + tid * 4);
            CP_COMMIT();
            CP_WAIT(1);
        } else {
            CP_WAIT(0);
        }
        __syncthreads();

        const uint32_t bufoff = (uint32_t)cur * ATILEB;

        // ---- S = Q K^T  (B frags via ldmatrix) ----
        float s[8][4];
        #pragma unroll
        for (int ni = 0; ni < 8; ni++)
            #pragma unroll
            for (int r = 0; r < 4; r++) s[ni][r] = 0.f;

        #pragma unroll
        for (int kk = 0; kk < 4; kk++) {
            const uint32_t coff = bufoff + kk * 32;
            #pragma unroll
            for (int j = 0; j < 4; j++) {
                uint32_t t[4];
                ldsm_x4(t, kAddr[j] + coff);
                mma_f16(s[2 * j],     qf[kk][0], qf[kk][1], qf[kk][2], qf[kk][3], t[0], t[1]);
                mma_f16(s[2 * j + 1], qf[kk][0], qf[kk][1], qf[kk][2], qf[kk][3], t[2], t[3]);
            }
        }

        // ---- mask + tile max ----
        const bool diag = (kt == qt);
        float mt0 = -INFINITY, mt1 = -INFINITY;
        #pragma unroll
        for (int ni = 0; ni < 8; ni++) {
            const int c0 = ni * 8 + 2 * q, c1 = c0 + 1;
            const bool pm0 = pm_sh[cur][c0] != 0, pm1 = pm_sh[cur][c1] != 0;
            const int gc0 = kbase + c0, gc1 = kbase + c1;
            if (!(pm0 && (!diag || gc0 <= r0g))) s[ni][0] = -1e30f;
            if (!(pm1 && (!diag || gc1 <= r0g))) s[ni][1] = -1e30f;
            if (!(pm0 && (!diag || gc0 <= r1g))) s[ni][2] = -1e30f;
            if (!(pm1 && (!diag || gc1 <= r1g))) s[ni][3] = -1e30f;
            mt0 = fmaxf(mt0, fmaxf(s[ni][0], s[ni][1]));
            mt1 = fmaxf(mt1, fmaxf(s[ni][2], s[ni][3]));
        }
        mt0 = fmaxf(mt0, __shfl_xor_sync(0xffffffffu, mt0, 1));
        mt0 = fmaxf(mt0, __shfl_xor_sync(0xffffffffu, mt0, 2));
        mt1 = fmaxf(mt1, __shfl_xor_sync(0xffffffffu, mt1, 1));
        mt1 = fmaxf(mt1, __shfl_xor_sync(0xffffffffu, mt1, 2));

        const float mn0 = fmaxf(mr0, mt0), mn1 = fmaxf(mr1, mt1);
        const float ms0 = (mn0 < -1e29f) ? 0.f : mn0;
        const float ms1 = (mn1 < -1e29f) ? 0.f : mn1;
        const float corr0 = ex2(mr0 - ms0);
        const float corr1 = ex2(mr1 - ms1);
        mr0 = mn0; mr1 = mn1;
        l0 *= corr0; l1 *= corr1;
        #pragma unroll
        for (int ni = 0; ni < 8; ni++) {
            o[ni][0] *= corr0; o[ni][1] *= corr0;
            o[ni][2] *= corr1; o[ni][3] *= corr1;
        }

        // ---- P = 2^(S-m): directly into A-fragment registers ----
        uint32_t pf[8][2];
        #pragma unroll
        for (int ni = 0; ni < 8; ni++) {
            float p0 = ex2(s[ni][0] - ms0);
            float p1 = ex2(s[ni][1] - ms0);
            float p2 = ex2(s[ni][2] - ms1);
            float p3 = ex2(s[ni][3] - ms1);
            l0 += p0 + p1; l1 += p2 + p3;
            pf[ni][0] = pack_h2(p0, p1);   // row g
            pf[ni][1] = pack_h2(p2, p3);   // row g+8
        }

        // ---- O += P V  (A from pf regs, B via ldmatrix from V^T) ----
        #pragma unroll
        for (int kk = 0; kk < 4; kk++) {
            const uint32_t coff = bufoff + kk * 32;
            const uint32_t a0 = pf[2 * kk][0], a1 = pf[2 * kk][1];
            const uint32_t a2 = pf[2 * kk + 1][0], a3 = pf[2 * kk + 1][1];
            #pragma unroll
            for (int j = 0; j < 4; j++) {
                uint32_t t[4];
                ldsm_x4(t, vAddr[j] + coff);
                mma_f16(o[2 * j],     a0, a1, a2, a3, t[0], t[1]);
                mma_f16(o[2 * j + 1], a0, a1, a2, a3, t[2], t[3]);
            }
        }
        __syncthreads();
    }

    // ---- finalize ----
    l0 += __shfl_xor_sync(0xffffffffu, l0, 1);
    l0 += __shfl_xor_sync(0xffffffffu, l0, 2);
    l1 += __shfl_xor_sync(0xffffffffu, l1, 1);
    l1 += __shfl_xor_sync(0xffffffffu, l1, 2);
    const float inv0 = 1.f / l0, inv1 = 1.f / l1;

    #pragma unroll
    for (int ni = 0; ni < 8; ni++) {
        const int wcol = h * 32 + ni * 4 + q;
        yh[(size_t)(b * T_ + r0g) * YW + wcol] = pack_h2(o[ni][0] * inv0, o[ni][1] * inv0);
        yh[(size_t)(b * T_ + r1g) * YW + wcol] = pack_h2(o[ni][2] * inv1, o[ni][3] * inv1);
    }
}

// ---------------------------------------------------------------------------
extern "C" void kernel_launch(void* const* d_in, const int* in_sizes, int n_in,
                              void* d_out, int out_size)
{
    const float* x      = (const float*)d_in[0];
    const float* W_kqv  = (const float*)d_in[1];
    const float* b_kqv  = (const float*)d_in[2];
    const float* W_proj = (const float*)d_in[3];
    const float* b_proj = (const float*)d_in[4];
    const int*   pmask  = (const int*)d_in[5];
    float* out = (float*)d_out;

    uint32_t *xh, *wkqvTh, *wprojTh, *kqvh, *vTh, *yh;
    cudaGetSymbolAddress((void**)&xh, g_xh);
    cudaGetSymbolAddress((void**)&wkqvTh, g_wkqvTh);
    cudaGetSymbolAddress((void**)&wprojTh, g_wprojTh);
    cudaGetSymbolAddress((void**)&kqvh, g_kqvh);
    cudaGetSymbolAddress((void**)&vTh, g_vTh);
    cudaGetSymbolAddress((void**)&yh, g_yh);

    // 0) convert x and weights to fp16
    {
        int nw = M_ * C_ / 2;
        cvt_f32_to_h2<<<(nw + 255) / 256, 256>>>(x, xh, nw);
        dim3 g1(C3_ / 32, C_ / 32);
        transpose_h<<<g1, dim3(32, 8)>>>(W_kqv, (__half*)wkqvTh, C_, C3_);
        dim3 g2(C_ / 32, C_ / 32);
        transpose_h<<<g2, dim3(32, 8)>>>(W_proj, (__half*)wprojTh, C_, C_);
    }
    // 1) kqv = x @ W_kqv + b_kqv
    {
        dim3 grid(C3_ / 128, M_ / 128);
        gemm_f16_mma<<<grid, 256>>>(xh, wkqvTh, b_kqv, kqvh, M_, C3_, K2_, 1);
    }
    // 2) V transpose per head
    {
        dim3 grid(T_ / 64, B_ * H_);
        transpose_v<<<grid, 128>>>(kqvh, vTh);
    }
    // 3) flash attention
    {
        dim3 grid(T_ / FBQ, B_ * H_);
        flash_attn_f16<<<grid, 128>>>(kqvh, vTh, pmask, yh);
    }
    // 4) out = y @ W_proj + b_proj
    {
        dim3 grid(C_ / 128, M_ / 128);
        gemm_f16_mma<<<grid, 256>>>(yh, wprojTh, b_proj, out, M_, C_, K2_, 0);
    }
}

// round 13
// speedup vs baseline: 2.2613x; 1.0757x over previous
#include <cuda_runtime.h>
#include <cuda_fp16.h>
#include <math.h>
#include <stdint.h>

#define B_ 4
#define T_ 2048
#define C_ 1024
#define H_ 16
#define D_ 64
#define C3_ (3 * C_)
#define M_ (B_ * T_)
#define K2_ (C_ / 2)          // 512 words (fp16 pairs)
#define KQV_W (C3_ / 2)       // 1536 words per token row
#define YW (C_ / 2)           // 512 words per token row

// ---------------------------------------------------------------------------
// Scratch (no cudaMalloc allowed)
// ---------------------------------------------------------------------------
__device__ uint32_t g_xh[(size_t)M_ * K2_];
__device__ uint32_t g_wkqvTh[(size_t)C3_ * K2_];
__device__ uint32_t g_wprojTh[(size_t)C_ * K2_];
__device__ uint32_t g_kqvh[(size_t)M_ * KQV_W];
__device__ uint32_t g_yh[(size_t)M_ * YW];

__device__ __forceinline__ uint32_t pack_h2(float a, float b) {
    __half2 h = __floats2half2_rn(a, b);
    return *reinterpret_cast<uint32_t*>(&h);
}
__device__ __forceinline__ float ex2(float x) {
    float y;
    asm("ex2.approx.f32 %0, %1;" : "=f"(y) : "f"(x));
    return y;
}

// mma.sync m16n8k16 fp16 in, fp32 accum
__device__ __forceinline__ void mma_f16(
    float c[4], uint32_t a0, uint32_t a1, uint32_t a2, uint32_t a3,
    uint32_t b0, uint32_t b1)
{
    asm volatile(
        "mma.sync.aligned.m16n8k16.row.col.f32.f16.f16.f32 "
        "{%0,%1,%2,%3}, {%4,%5,%6,%7}, {%8,%9}, {%0,%1,%2,%3};"
        : "+f"(c[0]), "+f"(c[1]), "+f"(c[2]), "+f"(c[3])
        : "r"(a0), "r"(a1), "r"(a2), "r"(a3), "r"(b0), "r"(b1));
}

// ldmatrix x4
__device__ __forceinline__ void ldsm_x4(uint32_t r[4], uint32_t addr) {
    asm volatile(
        "ldmatrix.sync.aligned.m8n8.x4.shared.b16 {%0,%1,%2,%3}, [%4];"
        : "=r"(r[0]), "=r"(r[1]), "=r"(r[2]), "=r"(r[3]) : "r"(addr));
}
// ldmatrix x4 transposed (for V: loads V^T fragments from [token][d] layout)
__device__ __forceinline__ void ldsm_x4_trans(uint32_t r[4], uint32_t addr) {
    asm volatile(
        "ldmatrix.sync.aligned.m8n8.x4.trans.shared.b16 {%0,%1,%2,%3}, [%4];"
        : "=r"(r[0]), "=r"(r[1]), "=r"(r[2]), "=r"(r[3]) : "r"(addr));
}

// cp.async 16B, L1-bypass
__device__ __forceinline__ void cp_async16(uint32_t smem_addr, const void* gptr) {
    asm volatile("cp.async.cg.shared.global [%0], [%1], 16;"
                 :: "r"(smem_addr), "l"(gptr));
}
#define CP_COMMIT() asm volatile("cp.async.commit_group;" ::: "memory")
#define CP_WAIT(N) asm volatile("cp.async.wait_group %0;" :: "n"(N) : "memory")

// ---------------------------------------------------------------------------
// fp32 -> fp16 pairs
// ---------------------------------------------------------------------------
__global__ void __launch_bounds__(256) cvt_f32_to_h2(
    const float* __restrict__ in, uint32_t* __restrict__ out, int nw)
{
    int i = blockIdx.x * blockDim.x + threadIdx.x;
    if (i >= nw) return;
    float2 v = ((const float2*)in)[i];
    out[i] = pack_h2(v.x, v.y);
}

// ---------------------------------------------------------------------------
// Transpose + fp16: W [K,N] fp32 -> Wt [N,K] fp16
// ---------------------------------------------------------------------------
__global__ void __launch_bounds__(256) transpose_h(
    const float* __restrict__ W, __half* __restrict__ Wt, int K, int N)
{
    __shared__ float tile[32][33];
    const int n0 = blockIdx.x * 32, k0 = blockIdx.y * 32;
    #pragma unroll
    for (int i = threadIdx.y; i < 32; i += 8)
        tile[i][threadIdx.x] = W[(size_t)(k0 + i) * N + n0 + threadIdx.x];
    __syncthreads();
    #pragma unroll
    for (int i = threadIdx.y; i < 32; i += 8)
        Wt[(size_t)(n0 + i) * K + k0 + threadIdx.x] = __float2half_rn(tile[threadIdx.x][i]);
}

// ---------------------------------------------------------------------------
// fp16 GEMM: 3-stage cp.async pipeline (dynamic smem), ldmatrix frags:
//   C[M,N] = A[M,K] @ Bt[N,K]^T + bias[N]
// CTA 128x128, BK=16 words (32 fp16), 256 threads (8 warps 2x4, warp 64x32).
// ---------------------------------------------------------------------------
#define GBK2 16
#define SP 20
#define GSTG (128 * SP)                 // words per stage per operand
#define GSTGB (GSTG * 4)                // bytes per stage
#define GSM_DYN (3 * 2 * GSTGB)         // 61440 bytes

__global__ void __launch_bounds__(256, 2) gemm_f16_mma(
    const uint32_t* __restrict__ A, const uint32_t* __restrict__ Bt,
    const float* __restrict__ bias, void* __restrict__ Cout,
    int M, int N, int K2, int outHalf)
{
    extern __shared__ uint32_t dsm[];
    uint32_t* Asm = dsm;                // 3 stages
    uint32_t* Bsm = dsm + 3 * GSTG;     // 3 stages

    const int tid = threadIdx.x;
    const int wid = tid >> 5;
    const int lane = tid & 31;
    const int g = lane >> 2;
    const int q = lane & 3;
    const int i8 = lane & 7, mh = lane >> 3;

    const int wm = (wid >> 2) * 64;
    const int wn = (wid & 3) * 32;

    const int mtile = blockIdx.y;
    const int ntile = blockIdx.x;

    const uint32_t* Ag = A + (size_t)mtile * 128 * K2;
    const uint32_t* Bg = Bt + (size_t)ntile * 128 * K2;

    const uint32_t asA = (uint32_t)__cvta_generic_to_shared(Asm);
    const uint32_t asB = (uint32_t)__cvta_generic_to_shared(Bsm);

    // ldmatrix per-lane base addresses (stage/ks offsets added in-loop)
    uint32_t aAddr[4];
    #pragma unroll
    for (int mi = 0; mi < 4; mi++)
        aAddr[mi] = asA + ((wm + mi * 16 + i8 + (mh & 1) * 8) * SP + (mh >> 1) * 4) * 4;
    uint32_t bAddr[2];
    #pragma unroll
    for (int j = 0; j < 2; j++)
        bAddr[j] = asB + ((wn + (2 * j + (mh >> 1)) * 8 + i8) * SP + (mh & 1) * 4) * 4;

    const int lr = tid >> 2, lc = tid & 3;
    const int nchunk = K2 / GBK2;

    // prologue: stages 0, 1
    #pragma unroll
    for (int s = 0; s < 2; s++) {
        const int k0 = s * GBK2;
        const uint32_t boff = (uint32_t)(s * GSTG) * 4;
        #pragma unroll
        for (int i = 0; i < 2; i++) {
            const int r = lr + i * 64;
            const uint32_t doff = boff + (uint32_t)(r * SP + lc * 4) * 4;
            cp_async16(asA + doff, Ag + (size_t)r * K2 + k0 + lc * 4);
            cp_async16(asB + doff, Bg + (size_t)r * K2 + k0 + lc * 4);
        }
        CP_COMMIT();
    }

    float acc[4][4][4];
    #pragma unroll
    for (int mi = 0; mi < 4; mi++)
        #pragma unroll
        for (int ni = 0; ni < 4; ni++)
            #pragma unroll
            for (int r = 0; r < 4; r++) acc[mi][ni][r] = 0.f;

    int stage = 0;
    for (int ch = 0; ch < nchunk; ch++) {
        CP_WAIT(1);            // group for stage ch complete
        __syncthreads();       // all warps past compute of ch-1; data visible

        // prefetch ch+2 into the stage freed at iter ch-1
        if (ch + 2 < nchunk) {
            const int k0 = (ch + 2) * GBK2;
            int ps = stage + 2; if (ps >= 3) ps -= 3;
            const uint32_t boff = (uint32_t)(ps * GSTG) * 4;
            #pragma unroll
            for (int i = 0; i < 2; i++) {
                const int r = lr + i * 64;
                const uint32_t doff = boff + (uint32_t)(r * SP + lc * 4) * 4;
                cp_async16(asA + doff, Ag + (size_t)r * K2 + k0 + lc * 4);
                cp_async16(asB + doff, Bg + (size_t)r * K2 + k0 + lc * 4);
            }
        }
        CP_COMMIT();           // always commit (possibly-empty group)

        const uint32_t bufoff = (uint32_t)stage * GSTGB;
        #pragma unroll
        for (int ks = 0; ks < GBK2; ks += 8) {
            const uint32_t coff = bufoff + ks * 4;
            uint32_t af[4][4], bf[4][2];
            #pragma unroll
            for (int mi = 0; mi < 4; mi++)
                ldsm_x4(af[mi], aAddr[mi] + coff);
            #pragma unroll
            for (int j = 0; j < 2; j++) {
                uint32_t t[4];
                ldsm_x4(t, bAddr[j] + coff);
                bf[2 * j][0] = t[0]; bf[2 * j][1] = t[1];
                bf[2 * j + 1][0] = t[2]; bf[2 * j + 1][1] = t[3];
            }
            #pragma unroll
            for (int mi = 0; mi < 4; mi++)
                #pragma unroll
                for (int ni = 0; ni < 4; ni++)
                    mma_f16(acc[mi][ni], af[mi][0], af[mi][1], af[mi][2], af[mi][3],
                            bf[ni][0], bf[ni][1]);
        }
        if (++stage == 3) stage = 0;
    }

    const int rowbase = mtile * 128 + wm;
    const int colbase = ntile * 128 + wn;
    if (outHalf) {
        uint32_t* Ch = (uint32_t*)Cout;
        const int Nw = N >> 1;
        #pragma unroll
        for (int mi = 0; mi < 4; mi++) {
            #pragma unroll
            for (int ni = 0; ni < 4; ni++) {
                const int col = colbase + ni * 8 + 2 * q;
                const float bx = bias[col], by = bias[col + 1];
                const int r0 = rowbase + mi * 16 + g;
                const int wcol = col >> 1;
                Ch[(size_t)r0 * Nw + wcol] = pack_h2(acc[mi][ni][0] + bx, acc[mi][ni][1] + by);
                Ch[(size_t)(r0 + 8) * Nw + wcol] = pack_h2(acc[mi][ni][2] + bx, acc[mi][ni][3] + by);
            }
        }
    } else {
        float* Cf = (float*)Cout;
        #pragma unroll
        for (int mi = 0; mi < 4; mi++) {
            #pragma unroll
            for (int ni = 0; ni < 4; ni++) {
                const int col = colbase + ni * 8 + 2 * q;
                const float bx = bias[col], by = bias[col + 1];
                const int r0 = rowbase + mi * 16 + g;
                float2 v0 = make_float2(acc[mi][ni][0] + bx, acc[mi][ni][1] + by);
                float2 v1 = make_float2(acc[mi][ni][2] + bx, acc[mi][ni][3] + by);
                *(float2*)(Cf + (size_t)r0 * N + col) = v0;
                *(float2*)(Cf + (size_t)(r0 + 8) * N + col) = v1;
            }
        }
    }
}

// ---------------------------------------------------------------------------
// fp16 flash attention: cp.async double-buffered K/V (V straight from kqv,
// transposed in-register via ldmatrix.trans), P in registers, log2 softmax.
// ---------------------------------------------------------------------------
#define FBQ 64
#define FKV 64
#define AP 36
#define ATILE (FKV * AP)
#define ATILEB (ATILE * 4)

__global__ void __launch_bounds__(128) flash_attn_f16(
    const uint32_t* __restrict__ kqvh, const int* __restrict__ pmask,
    uint32_t* __restrict__ yh)
{
    __shared__ uint32_t Ksh[2][ATILE];
    __shared__ uint32_t Vsh[2][ATILE];     // V natural layout [token][d words]
    __shared__ uint32_t Qsh[FBQ * AP];
    __shared__ int pm_sh[2][FKV];

    const int qt = (T_ / FBQ - 1) - blockIdx.x;
    const int bh = blockIdx.y;
    const int b = bh / H_, h = bh % H_;
    const int tid = threadIdx.x;
    const int wid = tid >> 5, lane = tid & 31;
    const int g = lane >> 2, q = lane & 3;
    const int i8 = lane & 7, mh = lane >> 3;
    const int m0 = wid * 16;

    const uint32_t* baseW = kqvh + (size_t)b * T_ * KQV_W + h * 32;
    const int* pmrow = pmask + b * T_;

    const uint32_t sK = (uint32_t)__cvta_generic_to_shared(&Ksh[0][0]);
    const uint32_t sV = (uint32_t)__cvta_generic_to_shared(&Vsh[0][0]);
    const uint32_t sPM = (uint32_t)__cvta_generic_to_shared(&pm_sh[0][0]);

    // K (non-trans) B-frag addrs: rows = key, granule = k
    uint32_t kAddr[4];
    #pragma unroll
    for (int j = 0; j < 4; j++)
        kAddr[j] = sK + (((2 * j + (mh >> 1)) * 8 + i8) * AP + (mh & 1) * 4) * 4;
    // V (trans) B-frag addrs: rows = token (k), granule = d-octet (n)
    uint32_t vAddr[4];
    #pragma unroll
    for (int j = 0; j < 4; j++)
        vAddr[j] = sV + ((i8 + (mh & 1) * 8) * AP + (2 * j + (mh >> 1)) * 4) * 4;

    const int ir = tid >> 3, ic = tid & 7;

    // ---- load Q tile, scale by log2(e)/sqrt(D) ----
    const float qscale = 0.125f * 1.4426950408889634f;
    #pragma unroll
    for (int it = 0; it < 4; it++) {
        const int idx = tid + it * 128;
        const int r = idx >> 3, c4 = idx & 7;
        uint4 w = *(const uint4*)(baseW + (C_ / 2) + (size_t)(qt * FBQ + r) * KQV_W + c4 * 4);
        uint32_t* ww = &w.x;
        uint32_t out[4];
        #pragma unroll
        for (int k = 0; k < 4; k++) {
            __half2 hv = *reinterpret_cast<__half2*>(&ww[k]);
            float2 f = __half22float2(hv);
            out[k] = pack_h2(f.x * qscale, f.y * qscale);
        }
        *(uint4*)&Qsh[r * AP + c4 * 4] = *(uint4*)out;
    }

    // prologue: prefetch tile 0 into buf 0 (K part offset 0, V part offset 1024 words)
    {
        #pragma unroll
        for (int it = 0; it < 4; it++) {
            const int r = ir + it * 16;
            const uint32_t doff = (uint32_t)(r * AP + ic * 4) * 4;
            cp_async16(sK + doff, baseW + (size_t)r * KQV_W + ic * 4);
            cp_async16(sV + doff, baseW + 2 * (C_ / 2) + (size_t)r * KQV_W + ic * 4);
        }
        if (tid < 16) cp_async16(sPM + tid * 16, pmrow + tid * 4);
        CP_COMMIT();
    }
    __syncthreads();

    // ---- Q fragments ----
    uint32_t qf[4][4];
    #pragma unroll
    for (int kk = 0; kk < 4; kk++) {
        qf[kk][0] = Qsh[(m0 + g) * AP + kk * 8 + q];
        qf[kk][1] = Qsh[(m0 + 8 + g) * AP + kk * 8 + q];
        qf[kk][2] = Qsh[(m0 + g) * AP + kk * 8 + q + 4];
        qf[kk][3] = Qsh[(m0 + 8 + g) * AP + kk * 8 + q + 4];
    }

    float o[8][4];
    #pragma unroll
    for (int ni = 0; ni < 8; ni++)
        #pragma unroll
        for (int r = 0; r < 4; r++) o[ni][r] = 0.f;

    float mr0 = -INFINITY, mr1 = -INFINITY;
    float l0 = 0.f, l1 = 0.f;

    const int r0g = qt * FBQ + m0 + g;
    const int r1g = r0g + 8;

    for (int kt = 0; kt <= qt; kt++) {
        const int cur = kt & 1;
        const int kbase = kt * FKV;

        if (kt < qt) {
            const int nb = kbase + FKV;
            const uint32_t boff = (uint32_t)((cur ^ 1) * ATILE) * 4;
            #pragma unroll
            for (int it = 0; it < 4; it++) {
                const int r = ir + it * 16;
                const uint32_t doff = boff + (uint32_t)(r * AP + ic * 4) * 4;
                cp_async16(sK + doff, baseW + (size_t)(nb + r) * KQV_W + ic * 4);
                cp_async16(sV + doff, baseW + 2 * (C_ / 2) + (size_t)(nb + r) * KQV_W + ic * 4);
            }
            if (tid < 16) cp_async16(sPM + (cur ^ 1) * 256 + tid * 16, pmrow + nb + tid * 4);
            CP_COMMIT();
            CP_WAIT(1);
        } else {
            CP_WAIT(0);
        }
        __syncthreads();

        const uint32_t bufoff = (uint32_t)cur * ATILEB;

        // ---- S = Q K^T ----
        float s[8][4];
        #pragma unroll
        for (int ni = 0; ni < 8; ni++)
            #pragma unroll
            for (int r = 0; r < 4; r++) s[ni][r] = 0.f;

        #pragma unroll
        for (int kk = 0; kk < 4; kk++) {
            const uint32_t coff = bufoff + kk * 32;
            #pragma unroll
            for (int j = 0; j < 4; j++) {
                uint32_t t[4];
                ldsm_x4(t, kAddr[j] + coff);
                mma_f16(s[2 * j],     qf[kk][0], qf[kk][1], qf[kk][2], qf[kk][3], t[0], t[1]);
                mma_f16(s[2 * j + 1], qf[kk][0], qf[kk][1], qf[kk][2], qf[kk][3], t[2], t[3]);
            }
        }

        // ---- mask + tile max ----
        const bool diag = (kt == qt);
        float mt0 = -INFINITY, mt1 = -INFINITY;
        #pragma unroll
        for (int ni = 0; ni < 8; ni++) {
            const int c0 = ni * 8 + 2 * q, c1 = c0 + 1;
            const bool pm0 = pm_sh[cur][c0] != 0, pm1 = pm_sh[cur][c1] != 0;
            const int gc0 = kbase + c0, gc1 = kbase + c1;
            if (!(pm0 && (!diag || gc0 <= r0g))) s[ni][0] = -1e30f;
            if (!(pm1 && (!diag || gc1 <= r0g))) s[ni][1] = -1e30f;
            if (!(pm0 && (!diag || gc0 <= r1g))) s[ni][2] = -1e30f;
            if (!(pm1 && (!diag || gc1 <= r1g))) s[ni][3] = -1e30f;
            mt0 = fmaxf(mt0, fmaxf(s[ni][0], s[ni][1]));
            mt1 = fmaxf(mt1, fmaxf(s[ni][2], s[ni][3]));
        }
        mt0 = fmaxf(mt0, __shfl_xor_sync(0xffffffffu, mt0, 1));
        mt0 = fmaxf(mt0, __shfl_xor_sync(0xffffffffu, mt0, 2));
        mt1 = fmaxf(mt1, __shfl_xor_sync(0xffffffffu, mt1, 1));
        mt1 = fmaxf(mt1, __shfl_xor_sync(0xffffffffu, mt1, 2));

        const float mn0 = fmaxf(mr0, mt0), mn1 = fmaxf(mr1, mt1);
        const float ms0 = (mn0 < -1e29f) ? 0.f : mn0;
        const float ms1 = (mn1 < -1e29f) ? 0.f : mn1;
        const float corr0 = ex2(mr0 - ms0);
        const float corr1 = ex2(mr1 - ms1);
        mr0 = mn0; mr1 = mn1;
        l0 *= corr0; l1 *= corr1;
        #pragma unroll
        for (int ni = 0; ni < 8; ni++) {
            o[ni][0] *= corr0; o[ni][1] *= corr0;
            o[ni][2] *= corr1; o[ni][3] *= corr1;
        }

        // ---- P = 2^(S-m) directly into A-fragment registers ----
        uint32_t pf[8][2];
        #pragma unroll
        for (int ni = 0; ni < 8; ni++) {
            float p0 = ex2(s[ni][0] - ms0);
            float p1 = ex2(s[ni][1] - ms0);
            float p2 = ex2(s[ni][2] - ms1);
            float p3 = ex2(s[ni][3] - ms1);
            l0 += p0 + p1; l1 += p2 + p3;
            pf[ni][0] = pack_h2(p0, p1);
            pf[ni][1] = pack_h2(p2, p3);
        }

        // ---- O += P V  (B frags via ldmatrix.trans from natural V rows) ----
        #pragma unroll
        for (int kk = 0; kk < 4; kk++) {
            const uint32_t coff = bufoff + (uint32_t)(kk * 16 * AP) * 4;  // +16 token rows
            const uint32_t a0 = pf[2 * kk][0], a1 = pf[2 * kk][1];
            const uint32_t a2 = pf[2 * kk + 1][0], a3 = pf[2 * kk + 1][1];
            #pragma unroll
            for (int j = 0; j < 4; j++) {
                uint32_t t[4];
                ldsm_x4_trans(t, vAddr[j] + coff);
                mma_f16(o[2 * j],     a0, a1, a2, a3, t[0], t[1]);
                mma_f16(o[2 * j + 1], a0, a1, a2, a3, t[2], t[3]);
            }
        }
        __syncthreads();
    }

    // ---- finalize ----
    l0 += __shfl_xor_sync(0xffffffffu, l0, 1);
    l0 += __shfl_xor_sync(0xffffffffu, l0, 2);
    l1 += __shfl_xor_sync(0xffffffffu, l1, 1);
    l1 += __shfl_xor_sync(0xffffffffu, l1, 2);
    const float inv0 = 1.f / l0, inv1 = 1.f / l1;

    #pragma unroll
    for (int ni = 0; ni < 8; ni++) {
        const int wcol = h * 32 + ni * 4 + q;
        yh[(size_t)(b * T_ + r0g) * YW + wcol] = pack_h2(o[ni][0] * inv0, o[ni][1] * inv0);
        yh[(size_t)(b * T_ + r1g) * YW + wcol] = pack_h2(o[ni][2] * inv1, o[ni][3] * inv1);
    }
}

// ---------------------------------------------------------------------------
extern "C" void kernel_launch(void* const* d_in, const int* in_sizes, int n_in,
                              void* d_out, int out_size)
{
    const float* x      = (const float*)d_in[0];
    const float* W_kqv  = (const float*)d_in[1];
    const float* b_kqv  = (const float*)d_in[2];
    const float* W_proj = (const float*)d_in[3];
    const float* b_proj = (const float*)d_in[4];
    const int*   pmask  = (const int*)d_in[5];
    float* out = (float*)d_out;

    uint32_t *xh, *wkqvTh, *wprojTh, *kqvh, *yh;
    cudaGetSymbolAddress((void**)&xh, g_xh);
    cudaGetSymbolAddress((void**)&wkqvTh, g_wkqvTh);
    cudaGetSymbolAddress((void**)&wprojTh, g_wprojTh);
    cudaGetSymbolAddress((void**)&kqvh, g_kqvh);
    cudaGetSymbolAddress((void**)&yh, g_yh);

    // allow 60KB dynamic smem for the GEMM (idempotent)
    cudaFuncSetAttribute(gemm_f16_mma,
                         cudaFuncAttributeMaxDynamicSharedMemorySize, GSM_DYN);

    // 0) convert x and weights to fp16
    {
        int nw = M_ * C_ / 2;
        cvt_f32_to_h2<<<(nw + 255) / 256, 256>>>(x, xh, nw);
        dim3 g1(C3_ / 32, C_ / 32);
        transpose_h<<<g1, dim3(32, 8)>>>(W_kqv, (__half*)wkqvTh, C_, C3_);
        dim3 g2(C_ / 32, C_ / 32);
        transpose_h<<<g2, dim3(32, 8)>>>(W_proj, (__half*)wprojTh, C_, C_);
    }
    // 1) kqv = x @ W_kqv + b_kqv
    {
        dim3 grid(C3_ / 128, M_ / 128);
        gemm_f16_mma<<<grid, 256, GSM_DYN>>>(xh, wkqvTh, b_kqv, kqvh, M_, C3_, K2_, 1);
    }
    // 2) flash attention (V transposed in-register via ldmatrix.trans)
    {
        dim3 grid(T_ / FBQ, B_ * H_);
        flash_attn_f16<<<grid, 128>>>(kqvh, pmask, yh);
    }
    // 3) out = y @ W_proj + b_proj
    {
        dim3 grid(C_ / 128, M_ / 128);
        gemm_f16_mma<<<grid, 256, GSM_DYN>>>(yh, wprojTh, b_proj, out, M_, C_, K2_, 0);
    }
}